// round 9
// baseline (speedup 1.0000x reference)
#include <cuda_runtime.h>
#include <cuda_bf16.h>
#include <cstdint>

#define B_   256
#define N_   144
#define M_   (B_ * N_)            // 36864 rows
#define SCALE_ 0.125f             // 64^-0.5

// ---------------- scratch (device globals: allocation-free rule) -------------
__device__ float g_kv [(size_t)M_ * 1024];
__device__ float g_q  [(size_t)M_ * 512];

// bf16 hi|lo split operands: [rows, 1024] = [hi(512) | lo(512)]
__device__ __nv_bfloat16 g_xte [(size_t)M_ * 1024];   // x + is_end*topo
__device__ __nv_bfloat16 g_xe  [(size_t)M_ * 1024];   // x
__device__ __nv_bfloat16 g_ae  [(size_t)M_ * 1024];   // attention out (written by attn)
__device__ __nv_bfloat16 g_wkve[(size_t)1024 * 1024];
__device__ __nv_bfloat16 g_wqe [(size_t)512 * 1024];
__device__ __nv_bfloat16 g_wpe [(size_t)512 * 1024];

// ---------------- helpers ------------------------------------------------------
__device__ __forceinline__ uint32_t smem_u32(const void* p) {
    uint32_t a;
    asm("{ .reg .u64 t; cvta.to.shared.u64 t, %1; cvt.u32.u64 %0, t; }" : "=r"(a) : "l"(p));
    return a;
}
__device__ __forceinline__ void ldsm_x4(uint32_t& r0, uint32_t& r1, uint32_t& r2,
                                        uint32_t& r3, uint32_t addr) {
    asm volatile("ldmatrix.sync.aligned.m8n8.x4.shared.b16 {%0,%1,%2,%3}, [%4];"
                 : "=r"(r0), "=r"(r1), "=r"(r2), "=r"(r3) : "r"(addr));
}
__device__ __forceinline__ void mma_bf16(float* c, uint32_t a0, uint32_t a1,
                                         uint32_t a2, uint32_t a3,
                                         uint32_t b0, uint32_t b1) {
    asm volatile(
        "mma.sync.aligned.m16n8k16.row.col.f32.bf16.bf16.f32 "
        "{%0,%1,%2,%3}, {%4,%5,%6,%7}, {%8,%9}, {%0,%1,%2,%3};"
        : "+f"(c[0]), "+f"(c[1]), "+f"(c[2]), "+f"(c[3])
        : "r"(a0), "r"(a1), "r"(a2), "r"(a3), "r"(b0), "r"(b1));
}
__device__ __forceinline__ void split1(float v, __nv_bfloat16& h, __nv_bfloat16& l) {
    h = __float2bfloat16_rn(v);
    l = __float2bfloat16_rn(v - __bfloat162float(h));
}
__device__ __forceinline__ void cp16(uint32_t dst, const void* src) {
    asm volatile("cp.async.cg.shared.global [%0], [%1], 16;" :: "r"(dst), "l"(src));
}
// packed f32x2
__device__ __forceinline__ unsigned long long pack2(float lo, float hi) {
    unsigned long long r;
    asm("mov.b64 %0, {%1, %2};" : "=l"(r) : "f"(lo), "f"(hi));
    return r;
}
__device__ __forceinline__ void fma2(unsigned long long& d, unsigned long long a, unsigned long long b) {
    asm("fma.rn.f32x2 %0, %1, %2, %0;" : "+l"(d) : "l"(a), "l"(b));
}
__device__ __forceinline__ float2 unpack2(unsigned long long v) {
    float2 r;
    asm("mov.b64 {%0, %1}, %2;" : "=f"(r.x), "=f"(r.y) : "l"(v));
    return r;
}

// ---------------- fp32 -> bf16 hi/lo split (single stream) --------------------
__global__ __launch_bounds__(256)
void split_bf16_kernel(const float4* __restrict__ in, __nv_bfloat16* __restrict__ out,
                       long total4)
{
    long i = (long)blockIdx.x * blockDim.x + threadIdx.x;
    if (i >= total4) return;
    float4 a = in[i];
    long idx = i * 4;
    long row = idx >> 9;
    int  col = (int)(idx & 511);
    float v[4] = { a.x, a.y, a.z, a.w };
    __nv_bfloat16 h[4], l[4];
#pragma unroll
    for (int j = 0; j < 4; j++) split1(v[j], h[j], l[j]);
    __nv_bfloat16* base = out + row * 1024 + col;
    *(uint2*)(base)       = *(uint2*)h;
    *(uint2*)(base + 512) = *(uint2*)l;
}

// dual: oxe = split(x), oxte = split(x + f*topo)
__global__ __launch_bounds__(256)
void split_dual_kernel(const float4* __restrict__ x, const float4* __restrict__ topo,
                       const int* __restrict__ flag,
                       __nv_bfloat16* __restrict__ oxe, __nv_bfloat16* __restrict__ oxte,
                       long total4)
{
    long i = (long)blockIdx.x * blockDim.x + threadIdx.x;
    if (i >= total4) return;
    float4 a = x[i];
    float4 tp = topo[i];
    float f = (*flag != 0) ? 1.f : 0.f;
    long idx = i * 4;
    long row = idx >> 9;
    int  col = (int)(idx & 511);
    float v1[4] = { a.x, a.y, a.z, a.w };
    float v2[4] = { a.x + f * tp.x, a.y + f * tp.y, a.z + f * tp.z, a.w + f * tp.w };
    __nv_bfloat16 h[4], l[4];
#pragma unroll
    for (int j = 0; j < 4; j++) split1(v1[j], h[j], l[j]);
    __nv_bfloat16* b1 = oxe + row * 1024 + col;
    *(uint2*)(b1)       = *(uint2*)h;
    *(uint2*)(b1 + 512) = *(uint2*)l;
#pragma unroll
    for (int j = 0; j < 4; j++) split1(v2[j], h[j], l[j]);
    __nv_bfloat16* b2 = oxte + row * 1024 + col;
    *(uint2*)(b2)       = *(uint2*)h;
    *(uint2*)(b2 + 512) = *(uint2*)l;
}

// ---------------- mma.sync bf16 GEMM (exact round-7 version) -------------------
#define GTILE   18432                     // 128 rows x 144 B
#define GBUF    (2 * GTILE)               // A + B per stage buffer
#define GEMM_SMEM (2 * GBUF)              // 73728, double buffered

__global__ __launch_bounds__(256, 2)
void gemm_mma_kernel(const __nv_bfloat16* __restrict__ A,
                     const __nv_bfloat16* __restrict__ Bw,
                     const float* __restrict__ bias,
                     float* __restrict__ C, int Nc)
{
    extern __shared__ __align__(128) char smem[];
    const uint32_t sbase = smem_u32(smem);

    const int t    = threadIdx.x;
    const int lane = t & 31;
    const int w    = t >> 5;
    const int wm   = w >> 2;
    const int wn   = w & 3;
    const int row0 = blockIdx.y * 128;
    const int col0 = blockIdx.x * 128;

    const uint32_t aLane = sbase + (uint32_t)(wm * 64 + (lane & 15)) * 144 + (lane >> 4) * 16;
    const uint32_t bLane = sbase + GTILE
                         + (uint32_t)(wn * 32 + (lane & 7) + ((lane >> 4) & 1) * 8) * 144
                         + ((lane >> 3) & 1) * 16;

    float acc[4][4][4];
#pragma unroll
    for (int mi = 0; mi < 4; mi++)
#pragma unroll
        for (int nj = 0; nj < 4; nj++)
#pragma unroll
            for (int e = 0; e < 4; e++) acc[mi][nj][e] = 0.f;

    const int rowT = t >> 3;
    const int chT  = t & 7;
    const __nv_bfloat16* Ag = A  + (size_t)(row0 + rowT) * 1024 + chT * 8;
    const __nv_bfloat16* Bg = Bw + (size_t)(col0 + rowT) * 1024 + chT * 8;
    const uint32_t stA = sbase + (uint32_t)rowT * 144 + chT * 16;
    const uint32_t stB = stA + GTILE;

    auto stage = [&](int c, uint32_t bufOff) {
        const int s  = c >> 3;
        const int k0 = (c & 7) * 64;
        const int aCol = ((s == 1) ? 512 : 0) + k0;
        const int bCol = ((s == 2) ? 512 : 0) + k0;
#pragma unroll
        for (int j = 0; j < 4; j++) {
            cp16(stA + bufOff + j * 32 * 144, Ag + (size_t)j * 32 * 1024 + aCol);
            cp16(stB + bufOff + j * 32 * 144, Bg + (size_t)j * 32 * 1024 + bCol);
        }
        asm volatile("cp.async.commit_group;" ::: "memory");
    };

    stage(0, 0);
    for (int c = 0; c < 24; c++) {
        asm volatile("cp.async.wait_group 0;" ::: "memory");
        __syncthreads();
        if (c < 23) stage(c + 1, (uint32_t)((c + 1) & 1) * GBUF);
        const uint32_t bufOff = (uint32_t)(c & 1) * GBUF;

#pragma unroll
        for (int ks = 0; ks < 4; ks++) {
            uint32_t ar[4][4], br[2][4];
#pragma unroll
            for (int mi = 0; mi < 4; mi++)
                ldsm_x4(ar[mi][0], ar[mi][1], ar[mi][2], ar[mi][3],
                        aLane + bufOff + (uint32_t)mi * 16 * 144 + ks * 32);
#pragma unroll
            for (int pj = 0; pj < 2; pj++)
                ldsm_x4(br[pj][0], br[pj][1], br[pj][2], br[pj][3],
                        bLane + bufOff + (uint32_t)pj * 16 * 144 + ks * 32);
#pragma unroll
            for (int mi = 0; mi < 4; mi++)
#pragma unroll
                for (int nj = 0; nj < 4; nj++) {
                    const int pj = nj >> 1, hb = (nj & 1) * 2;
                    mma_bf16(acc[mi][nj], ar[mi][0], ar[mi][1], ar[mi][2], ar[mi][3],
                             br[pj][hb], br[pj][hb + 1]);
                }
        }
    }

    const int rbase = row0 + wm * 64 + (lane >> 2);
    const int cbase = col0 + wn * 32 + (lane & 3) * 2;
#pragma unroll
    for (int mi = 0; mi < 4; mi++) {
#pragma unroll
        for (int nj = 0; nj < 4; nj++) {
            const int r  = rbase + mi * 16;
            const int cc = cbase + nj * 8;
            float b0 = 0.f, b1 = 0.f;
            if (bias) { b0 = bias[cc]; b1 = bias[cc + 1]; }
            *(float2*)(C + (size_t)r * Nc + cc) =
                make_float2(acc[mi][nj][0] + b0, acc[mi][nj][1] + b1);
            *(float2*)(C + (size_t)(r + 8) * Nc + cc) =
                make_float2(acc[mi][nj][2] + b0, acc[mi][nj][3] + b1);
        }
    }
}

// ---------------- attention v4: fused bf16 hi/lo split epilogue ----------------
// Identical math to v3; output written directly as bf16 hi|lo rows of g_ae
// [m, 1024] = [hi(512) | lo(512)], eliminating the fp32 g_att round-trip.
#define AP   145
#define VP   68
#define QT_OFF 0
#define KT_OFF (64 * AP)
#define V_OFF  (2 * 64 * AP)
#define PT_OFF (2 * 64 * AP + 144 * VP)
#define ATTN_SMEM_FLOATS (2 * 64 * AP + 144 * VP + 144 * AP)
#define ATTN_SMEM_BYTES  (ATTN_SMEM_FLOATS * 4)

__global__ __launch_bounds__(256, 1)
void attn_kernel(const float* __restrict__ q, const float* __restrict__ kv,
                 __nv_bfloat16* __restrict__ oe)
{
    extern __shared__ float sm[];
    float* Qt = sm + QT_OFF;
    float* Kt = sm + KT_OFF;
    float* Vs = sm + V_OFF;
    float* Pt = sm + PT_OFF;
    float* red = Pt;

    const int b = blockIdx.x >> 3;
    const int h = blockIdx.x & 7;
    const int t = threadIdx.x;
    const int ty = t >> 4;
    const int tx = t & 15;

    const float* qb = q  + (size_t)b * 144 * 512  + h * 64;
    const float* kb = kv + (size_t)b * 144 * 1024 + h * 64;
    const float* vb = kb + 512;

    for (int i = t; i < 144 * 64; i += 256) {
        int r = i >> 6, k = i & 63;
        Qt[k * AP + r] = qb[(size_t)r * 512 + k] * SCALE_;
        Kt[k * AP + r] = kb[(size_t)r * 1024 + k];
    }
    for (int i = t; i < 144 * 16; i += 256) {
        int n = i >> 4, cc = (i & 15) << 2;
        *(float4*)(Vs + n * VP + cc) = *(const float4*)(vb + (size_t)n * 1024 + cc);
    }
    __syncthreads();

    unsigned long long acc2[9][4];
    float acc8[9];
#pragma unroll
    for (int i = 0; i < 9; i++) {
#pragma unroll
        for (int jp = 0; jp < 4; jp++) acc2[i][jp] = 0ull;
        acc8[i] = 0.f;
    }

    const float* Qb = Qt + ty * 9;
    const float* Kb = Kt + tx * 9;
#pragma unroll 2
    for (int k = 0; k < 64; k++) {
        float qv[9], kvv[9];
#pragma unroll
        for (int i = 0; i < 9; i++) qv[i]  = Qb[k * AP + i];
#pragma unroll
        for (int j = 0; j < 9; j++) kvv[j] = Kb[k * AP + j];
        unsigned long long kp[4] = { pack2(kvv[0], kvv[1]), pack2(kvv[2], kvv[3]),
                                     pack2(kvv[4], kvv[5]), pack2(kvv[6], kvv[7]) };
#pragma unroll
        for (int i = 0; i < 9; i++) {
            unsigned long long qd = pack2(qv[i], qv[i]);
#pragma unroll
            for (int jp = 0; jp < 4; jp++) fma2(acc2[i][jp], qd, kp[jp]);
            acc8[i] += qv[i] * kvv[8];
        }
    }

    float s[9][9];
#pragma unroll
    for (int i = 0; i < 9; i++) {
#pragma unroll
        for (int jp = 0; jp < 4; jp++) {
            float2 u = unpack2(acc2[i][jp]);
            s[i][2 * jp]     = u.x;
            s[i][2 * jp + 1] = u.y;
        }
        s[i][8] = acc8[i];
    }

#pragma unroll
    for (int i = 0; i < 9; i++) {
        float m = s[i][0];
#pragma unroll
        for (int j = 1; j < 9; j++) m = fmaxf(m, s[i][j]);
        red[(ty * 9 + i) * 17 + tx] = m;
    }
    __syncthreads();
    float mrow[9];
#pragma unroll
    for (int i = 0; i < 9; i++) {
        const float* rr = red + (ty * 9 + i) * 17;
        float m = rr[0];
#pragma unroll
        for (int u = 1; u < 16; u++) m = fmaxf(m, rr[u]);
        mrow[i] = m;
    }
    __syncthreads();
#pragma unroll
    for (int i = 0; i < 9; i++) {
        float sum = 0.f;
#pragma unroll
        for (int j = 0; j < 9; j++) {
            float e = __expf(s[i][j] - mrow[i]);
            s[i][j] = e;
            sum += e;
        }
        red[(ty * 9 + i) * 17 + tx] = sum;
    }
    __syncthreads();
    float inv[9];
#pragma unroll
    for (int i = 0; i < 9; i++) {
        const float* rr = red + (ty * 9 + i) * 17;
        float sum = rr[0];
#pragma unroll
        for (int u = 1; u < 16; u++) sum += rr[u];
        inv[i] = 1.f / sum;
    }
    __syncthreads();

#pragma unroll
    for (int j = 0; j < 9; j++)
#pragma unroll
        for (int i = 0; i < 9; i++)
            Pt[(tx * 9 + j) * AP + (ty * 9 + i)] = s[i][j];
    __syncthreads();

    unsigned long long out2[9][2];
#pragma unroll
    for (int i = 0; i < 9; i++) { out2[i][0] = 0ull; out2[i][1] = 0ull; }

    const float* Pb = Pt + ty * 9;
#pragma unroll 2
    for (int j = 0; j < 144; j++) {
        float pv[9];
#pragma unroll
        for (int i = 0; i < 9; i++) pv[i] = Pb[j * AP + i];
        float4 vv = *(const float4*)(Vs + j * VP + tx * 4);
        unsigned long long v01 = pack2(vv.x, vv.y);
        unsigned long long v23 = pack2(vv.z, vv.w);
#pragma unroll
        for (int i = 0; i < 9; i++) {
            unsigned long long pd = pack2(pv[i], pv[i]);
            fma2(out2[i][0], pd, v01);
            fma2(out2[i][1], pd, v23);
        }
    }

    // fused epilogue: write bf16 hi|lo rows of [m, 1024]; col = h*64 + tx*4
    __nv_bfloat16* ob = oe + ((size_t)b * 144) * 1024 + h * 64 + tx * 4;
#pragma unroll
    for (int i = 0; i < 9; i++) {
        int r = ty * 9 + i;
        float2 o01 = unpack2(out2[i][0]);
        float2 o23 = unpack2(out2[i][1]);
        float v[4] = { o01.x * inv[i], o01.y * inv[i], o23.x * inv[i], o23.y * inv[i] };
        __nv_bfloat16 hh[4], ll[4];
#pragma unroll
        for (int u = 0; u < 4; u++) split1(v[u], hh[u], ll[u]);
        __nv_bfloat16* dst = ob + (size_t)r * 1024;
        *(uint2*)(dst)       = *(uint2*)hh;
        *(uint2*)(dst + 512) = *(uint2*)ll;
    }
}

// ---------------- launch -------------------------------------------------------
extern "C" void kernel_launch(void* const* d_in, const int* in_sizes, int n_in,
                              void* d_out, int out_size)
{
    const float* x      = (const float*)d_in[0];
    const float* topo   = (const float*)d_in[1];
    const float* kv_w   = (const float*)d_in[2];
    const float* q_w    = (const float*)d_in[3];
    const float* proj_w = (const float*)d_in[4];
    const float* proj_b = (const float*)d_in[5];
    const int*   is_end = (const int*)d_in[6];

    void *pkv, *pq, *pxte, *pxe, *pae, *pwkv, *pwq, *pwp;
    cudaGetSymbolAddress(&pkv,  g_kv);
    cudaGetSymbolAddress(&pq,   g_q);
    cudaGetSymbolAddress(&pxte, g_xte);
    cudaGetSymbolAddress(&pxe,  g_xe);
    cudaGetSymbolAddress(&pae,  g_ae);
    cudaGetSymbolAddress(&pwkv, g_wkve);
    cudaGetSymbolAddress(&pwq,  g_wqe);
    cudaGetSymbolAddress(&pwp,  g_wpe);

    cudaFuncSetAttribute(attn_kernel, cudaFuncAttributeMaxDynamicSharedMemorySize,
                         ATTN_SMEM_BYTES);
    cudaFuncSetAttribute(gemm_mma_kernel, cudaFuncAttributeMaxDynamicSharedMemorySize,
                         GEMM_SMEM);

    const long act4 = (long)M_ * 512 / 4;
    const long wkv4 = 1024L * 512 / 4;
    const long w4   = 512L * 512 / 4;
    const int  TB   = 256;

    split_dual_kernel<<<(unsigned)((act4 + TB - 1) / TB), TB>>>(
        (const float4*)x, (const float4*)topo, is_end,
        (__nv_bfloat16*)pxe, (__nv_bfloat16*)pxte, act4);
    split_bf16_kernel<<<(unsigned)((wkv4 + TB - 1) / TB), TB>>>(
        (const float4*)kv_w, (__nv_bfloat16*)pwkv, wkv4);
    split_bf16_kernel<<<(unsigned)((w4 + TB - 1) / TB), TB>>>(
        (const float4*)q_w, (__nv_bfloat16*)pwq, w4);
    split_bf16_kernel<<<(unsigned)((w4 + TB - 1) / TB), TB>>>(
        (const float4*)proj_w, (__nv_bfloat16*)pwp, w4);

    gemm_mma_kernel<<<dim3(8, 288), 256, GEMM_SMEM>>>(
        (const __nv_bfloat16*)pxte, (const __nv_bfloat16*)pwkv, nullptr, (float*)pkv, 1024);
    gemm_mma_kernel<<<dim3(4, 288), 256, GEMM_SMEM>>>(
        (const __nv_bfloat16*)pxe, (const __nv_bfloat16*)pwq, nullptr, (float*)pq, 512);
    // attention writes bf16 hi|lo directly (fused split)
    attn_kernel<<<B_ * 8, 256, ATTN_SMEM_BYTES>>>(
        (float*)pq, (float*)pkv, (__nv_bfloat16*)pae);
    gemm_mma_kernel<<<dim3(4, 288), 256, GEMM_SMEM>>>(
        (const __nv_bfloat16*)pae, (const __nv_bfloat16*)pwp, proj_b, (float*)d_out, 512);
}

// round 10
// speedup vs baseline: 1.4601x; 1.4601x over previous
#include <cuda_runtime.h>
#include <cuda_bf16.h>
#include <cstdint>

#define B_   256
#define N_   144
#define M_   (B_ * N_)            // 36864 rows
#define SCALE_ 0.125f             // 64^-0.5

// ---------------- scratch (device globals: allocation-free rule) -------------
__device__ float g_kv [(size_t)M_ * 1024];
__device__ float g_q  [(size_t)M_ * 512];
__device__ float g_att[(size_t)M_ * 512];

// bf16 hi|lo split operands: [rows, 1024] = [hi(512) | lo(512)]
__device__ __nv_bfloat16 g_xte [(size_t)M_ * 1024];   // x + is_end*topo
__device__ __nv_bfloat16 g_xe  [(size_t)M_ * 1024];   // x
__device__ __nv_bfloat16 g_ae  [(size_t)M_ * 1024];   // attention out
__device__ __nv_bfloat16 g_wkve[(size_t)1024 * 1024];
__device__ __nv_bfloat16 g_wqe [(size_t)512 * 1024];
__device__ __nv_bfloat16 g_wpe [(size_t)512 * 1024];

// ---------------- helpers ------------------------------------------------------
__device__ __forceinline__ uint32_t smem_u32(const void* p) {
    uint32_t a;
    asm("{ .reg .u64 t; cvta.to.shared.u64 t, %1; cvt.u32.u64 %0, t; }" : "=r"(a) : "l"(p));
    return a;
}
__device__ __forceinline__ void ldsm_x4(uint32_t& r0, uint32_t& r1, uint32_t& r2,
                                        uint32_t& r3, uint32_t addr) {
    asm volatile("ldmatrix.sync.aligned.m8n8.x4.shared.b16 {%0,%1,%2,%3}, [%4];"
                 : "=r"(r0), "=r"(r1), "=r"(r2), "=r"(r3) : "r"(addr));
}
__device__ __forceinline__ void mma_bf16(float* c, uint32_t a0, uint32_t a1,
                                         uint32_t a2, uint32_t a3,
                                         uint32_t b0, uint32_t b1) {
    asm volatile(
        "mma.sync.aligned.m16n8k16.row.col.f32.bf16.bf16.f32 "
        "{%0,%1,%2,%3}, {%4,%5,%6,%7}, {%8,%9}, {%0,%1,%2,%3};"
        : "+f"(c[0]), "+f"(c[1]), "+f"(c[2]), "+f"(c[3])
        : "r"(a0), "r"(a1), "r"(a2), "r"(a3), "r"(b0), "r"(b1));
}
__device__ __forceinline__ void split1(float v, __nv_bfloat16& h, __nv_bfloat16& l) {
    h = __float2bfloat16_rn(v);
    l = __float2bfloat16_rn(v - __bfloat162float(h));
}
__device__ __forceinline__ void cp16(uint32_t dst, const void* src) {
    asm volatile("cp.async.cg.shared.global [%0], [%1], 16;" :: "r"(dst), "l"(src));
}
// packed f32x2
__device__ __forceinline__ unsigned long long pack2(float lo, float hi) {
    unsigned long long r;
    asm("mov.b64 %0, {%1, %2};" : "=l"(r) : "f"(lo), "f"(hi));
    return r;
}
__device__ __forceinline__ void fma2(unsigned long long& d, unsigned long long a, unsigned long long b) {
    asm("fma.rn.f32x2 %0, %1, %2, %0;" : "+l"(d) : "l"(a), "l"(b));
}
__device__ __forceinline__ float2 unpack2(unsigned long long v) {
    float2 r;
    asm("mov.b64 {%0, %1}, %2;" : "=f"(r.x), "=f"(r.y) : "l"(v));
    return r;
}

// ---------------- fp32 -> bf16 hi/lo split (single stream) --------------------
__global__ __launch_bounds__(256)
void split_bf16_kernel(const float4* __restrict__ in, __nv_bfloat16* __restrict__ out,
                       long total4)
{
    long i = (long)blockIdx.x * blockDim.x + threadIdx.x;
    if (i >= total4) return;
    float4 a = in[i];
    long idx = i * 4;
    long row = idx >> 9;
    int  col = (int)(idx & 511);
    float v[4] = { a.x, a.y, a.z, a.w };
    __nv_bfloat16 h[4], l[4];
#pragma unroll
    for (int j = 0; j < 4; j++) split1(v[j], h[j], l[j]);
    __nv_bfloat16* base = out + row * 1024 + col;
    *(uint2*)(base)       = *(uint2*)h;
    *(uint2*)(base + 512) = *(uint2*)l;
}

// dual: oxe = split(x), oxte = split(x + f*topo)
__global__ __launch_bounds__(256)
void split_dual_kernel(const float4* __restrict__ x, const float4* __restrict__ topo,
                       const int* __restrict__ flag,
                       __nv_bfloat16* __restrict__ oxe, __nv_bfloat16* __restrict__ oxte,
                       long total4)
{
    long i = (long)blockIdx.x * blockDim.x + threadIdx.x;
    if (i >= total4) return;
    float4 a = x[i];
    float4 tp = topo[i];
    float f = (*flag != 0) ? 1.f : 0.f;
    long idx = i * 4;
    long row = idx >> 9;
    int  col = (int)(idx & 511);
    float v1[4] = { a.x, a.y, a.z, a.w };
    float v2[4] = { a.x + f * tp.x, a.y + f * tp.y, a.z + f * tp.z, a.w + f * tp.w };
    __nv_bfloat16 h[4], l[4];
#pragma unroll
    for (int j = 0; j < 4; j++) split1(v1[j], h[j], l[j]);
    __nv_bfloat16* b1 = oxe + row * 1024 + col;
    *(uint2*)(b1)       = *(uint2*)h;
    *(uint2*)(b1 + 512) = *(uint2*)l;
#pragma unroll
    for (int j = 0; j < 4; j++) split1(v2[j], h[j], l[j]);
    __nv_bfloat16* b2 = oxte + row * 1024 + col;
    *(uint2*)(b2)       = *(uint2*)h;
    *(uint2*)(b2 + 512) = *(uint2*)l;
}

// ---------------- mma.sync bf16 GEMM, 3-stage cp.async pipeline ----------------
// R7 compute/staging maps unchanged; only the buffer ring is deepened to 3 with
// wait_group 1 so one stage stays in flight under each compute section.
#define GTILE   18432                     // 128 rows x 144 B
#define GBUF    (2 * GTILE)               // A + B per stage buffer
#define GEMM_SMEM (3 * GBUF)              // 110592, triple buffered

__global__ __launch_bounds__(256, 2)
void gemm_mma_kernel(const __nv_bfloat16* __restrict__ A,
                     const __nv_bfloat16* __restrict__ Bw,
                     const float* __restrict__ bias,
                     float* __restrict__ C, int Nc)
{
    extern __shared__ __align__(128) char smem[];
    const uint32_t sbase = smem_u32(smem);

    const int t    = threadIdx.x;
    const int lane = t & 31;
    const int w    = t >> 5;
    const int wm   = w >> 2;
    const int wn   = w & 3;
    const int row0 = blockIdx.y * 128;
    const int col0 = blockIdx.x * 128;

    const uint32_t aLane = sbase + (uint32_t)(wm * 64 + (lane & 15)) * 144 + (lane >> 4) * 16;
    const uint32_t bLane = sbase + GTILE
                         + (uint32_t)(wn * 32 + (lane & 7) + ((lane >> 4) & 1) * 8) * 144
                         + ((lane >> 3) & 1) * 16;

    float acc[4][4][4];
#pragma unroll
    for (int mi = 0; mi < 4; mi++)
#pragma unroll
        for (int nj = 0; nj < 4; nj++)
#pragma unroll
            for (int e = 0; e < 4; e++) acc[mi][nj][e] = 0.f;

    const int rowT = t >> 3;
    const int chT  = t & 7;
    const __nv_bfloat16* Ag = A  + (size_t)(row0 + rowT) * 1024 + chT * 8;
    const __nv_bfloat16* Bg = Bw + (size_t)(col0 + rowT) * 1024 + chT * 8;
    const uint32_t stA = sbase + (uint32_t)rowT * 144 + chT * 16;
    const uint32_t stB = stA + GTILE;

    auto stage = [&](int c, uint32_t bufOff) {
        const int s  = c >> 3;
        const int k0 = (c & 7) * 64;
        const int aCol = ((s == 1) ? 512 : 0) + k0;
        const int bCol = ((s == 2) ? 512 : 0) + k0;
#pragma unroll
        for (int j = 0; j < 4; j++) {
            cp16(stA + bufOff + j * 32 * 144, Ag + (size_t)j * 32 * 1024 + aCol);
            cp16(stB + bufOff + j * 32 * 144, Bg + (size_t)j * 32 * 1024 + bCol);
        }
        asm volatile("cp.async.commit_group;" ::: "memory");
    };

    stage(0, 0);
    stage(1, GBUF);
    for (int c = 0; c < 24; c++) {
        if (c < 23) asm volatile("cp.async.wait_group 1;" ::: "memory");
        else        asm volatile("cp.async.wait_group 0;" ::: "memory");
        __syncthreads();               // stage(c) visible; buf (c-1)%3 readers done
        if (c < 22) stage(c + 2, (uint32_t)((c + 2) % 3) * GBUF);
        const uint32_t bufOff = (uint32_t)(c % 3) * GBUF;

#pragma unroll
        for (int ks = 0; ks < 4; ks++) {
            uint32_t ar[4][4], br[2][4];
#pragma unroll
            for (int mi = 0; mi < 4; mi++)
                ldsm_x4(ar[mi][0], ar[mi][1], ar[mi][2], ar[mi][3],
                        aLane + bufOff + (uint32_t)mi * 16 * 144 + ks * 32);
#pragma unroll
            for (int pj = 0; pj < 2; pj++)
                ldsm_x4(br[pj][0], br[pj][1], br[pj][2], br[pj][3],
                        bLane + bufOff + (uint32_t)pj * 16 * 144 + ks * 32);
#pragma unroll
            for (int mi = 0; mi < 4; mi++)
#pragma unroll
                for (int nj = 0; nj < 4; nj++) {
                    const int pj = nj >> 1, hb = (nj & 1) * 2;
                    mma_bf16(acc[mi][nj], ar[mi][0], ar[mi][1], ar[mi][2], ar[mi][3],
                             br[pj][hb], br[pj][hb + 1]);
                }
        }
    }

    const int rbase = row0 + wm * 64 + (lane >> 2);
    const int cbase = col0 + wn * 32 + (lane & 3) * 2;
#pragma unroll
    for (int mi = 0; mi < 4; mi++) {
#pragma unroll
        for (int nj = 0; nj < 4; nj++) {
            const int r  = rbase + mi * 16;
            const int cc = cbase + nj * 8;
            float b0 = 0.f, b1 = 0.f;
            if (bias) { b0 = bias[cc]; b1 = bias[cc + 1]; }
            *(float2*)(C + (size_t)r * Nc + cc) =
                make_float2(acc[mi][nj][0] + b0, acc[mi][nj][1] + b1);
            *(float2*)(C + (size_t)(r + 8) * Nc + cc) =
                make_float2(acc[mi][nj][2] + b0, acc[mi][nj][3] + b1);
        }
    }
}

// ---------------- attention v3 (exact round-7 version) ------------------------
#define AP   145
#define VP   68
#define QT_OFF 0
#define KT_OFF (64 * AP)
#define V_OFF  (2 * 64 * AP)
#define PT_OFF (2 * 64 * AP + 144 * VP)
#define ATTN_SMEM_FLOATS (2 * 64 * AP + 144 * VP + 144 * AP)
#define ATTN_SMEM_BYTES  (ATTN_SMEM_FLOATS * 4)

__global__ __launch_bounds__(256, 1)
void attn_kernel(const float* __restrict__ q, const float* __restrict__ kv,
                 float* __restrict__ o)
{
    extern __shared__ float sm[];
    float* Qt = sm + QT_OFF;
    float* Kt = sm + KT_OFF;
    float* Vs = sm + V_OFF;
    float* Pt = sm + PT_OFF;
    float* red = Pt;

    const int b = blockIdx.x >> 3;
    const int h = blockIdx.x & 7;
    const int t = threadIdx.x;
    const int ty = t >> 4;
    const int tx = t & 15;

    const float* qb = q  + (size_t)b * 144 * 512  + h * 64;
    const float* kb = kv + (size_t)b * 144 * 1024 + h * 64;
    const float* vb = kb + 512;

    for (int i = t; i < 144 * 64; i += 256) {
        int r = i >> 6, k = i & 63;
        Qt[k * AP + r] = qb[(size_t)r * 512 + k] * SCALE_;
        Kt[k * AP + r] = kb[(size_t)r * 1024 + k];
    }
    for (int i = t; i < 144 * 16; i += 256) {
        int n = i >> 4, cc = (i & 15) << 2;
        *(float4*)(Vs + n * VP + cc) = *(const float4*)(vb + (size_t)n * 1024 + cc);
    }
    __syncthreads();

    unsigned long long acc2[9][4];
    float acc8[9];
#pragma unroll
    for (int i = 0; i < 9; i++) {
#pragma unroll
        for (int jp = 0; jp < 4; jp++) acc2[i][jp] = 0ull;
        acc8[i] = 0.f;
    }

    const float* Qb = Qt + ty * 9;
    const float* Kb = Kt + tx * 9;
#pragma unroll 2
    for (int k = 0; k < 64; k++) {
        float qv[9], kvv[9];
#pragma unroll
        for (int i = 0; i < 9; i++) qv[i]  = Qb[k * AP + i];
#pragma unroll
        for (int j = 0; j < 9; j++) kvv[j] = Kb[k * AP + j];
        unsigned long long kp[4] = { pack2(kvv[0], kvv[1]), pack2(kvv[2], kvv[3]),
                                     pack2(kvv[4], kvv[5]), pack2(kvv[6], kvv[7]) };
#pragma unroll
        for (int i = 0; i < 9; i++) {
            unsigned long long qd = pack2(qv[i], qv[i]);
#pragma unroll
            for (int jp = 0; jp < 4; jp++) fma2(acc2[i][jp], qd, kp[jp]);
            acc8[i] += qv[i] * kvv[8];
        }
    }

    float s[9][9];
#pragma unroll
    for (int i = 0; i < 9; i++) {
#pragma unroll
        for (int jp = 0; jp < 4; jp++) {
            float2 u = unpack2(acc2[i][jp]);
            s[i][2 * jp]     = u.x;
            s[i][2 * jp + 1] = u.y;
        }
        s[i][8] = acc8[i];
    }

#pragma unroll
    for (int i = 0; i < 9; i++) {
        float m = s[i][0];
#pragma unroll
        for (int j = 1; j < 9; j++) m = fmaxf(m, s[i][j]);
        red[(ty * 9 + i) * 17 + tx] = m;
    }
    __syncthreads();
    float mrow[9];
#pragma unroll
    for (int i = 0; i < 9; i++) {
        const float* rr = red + (ty * 9 + i) * 17;
        float m = rr[0];
#pragma unroll
        for (int u = 1; u < 16; u++) m = fmaxf(m, rr[u]);
        mrow[i] = m;
    }
    __syncthreads();
#pragma unroll
    for (int i = 0; i < 9; i++) {
        float sum = 0.f;
#pragma unroll
        for (int j = 0; j < 9; j++) {
            float e = __expf(s[i][j] - mrow[i]);
            s[i][j] = e;
            sum += e;
        }
        red[(ty * 9 + i) * 17 + tx] = sum;
    }
    __syncthreads();
    float inv[9];
#pragma unroll
    for (int i = 0; i < 9; i++) {
        const float* rr = red + (ty * 9 + i) * 17;
        float sum = rr[0];
#pragma unroll
        for (int u = 1; u < 16; u++) sum += rr[u];
        inv[i] = 1.f / sum;
    }
    __syncthreads();

#pragma unroll
    for (int j = 0; j < 9; j++)
#pragma unroll
        for (int i = 0; i < 9; i++)
            Pt[(tx * 9 + j) * AP + (ty * 9 + i)] = s[i][j];
    __syncthreads();

    unsigned long long out2[9][2];
#pragma unroll
    for (int i = 0; i < 9; i++) { out2[i][0] = 0ull; out2[i][1] = 0ull; }

    const float* Pb = Pt + ty * 9;
#pragma unroll 2
    for (int j = 0; j < 144; j++) {
        float pv[9];
#pragma unroll
        for (int i = 0; i < 9; i++) pv[i] = Pb[j * AP + i];
        float4 vv = *(const float4*)(Vs + j * VP + tx * 4);
        unsigned long long v01 = pack2(vv.x, vv.y);
        unsigned long long v23 = pack2(vv.z, vv.w);
#pragma unroll
        for (int i = 0; i < 9; i++) {
            unsigned long long pd = pack2(pv[i], pv[i]);
            fma2(out2[i][0], pd, v01);
            fma2(out2[i][1], pd, v23);
        }
    }

    float* ob = o + (size_t)b * 144 * 512 + h * 64;
#pragma unroll
    for (int i = 0; i < 9; i++) {
        int r = ty * 9 + i;
        float2 o01 = unpack2(out2[i][0]);
        float2 o23 = unpack2(out2[i][1]);
        *(float4*)(ob + (size_t)r * 512 + tx * 4) =
            make_float4(o01.x * inv[i], o01.y * inv[i],
                        o23.x * inv[i], o23.y * inv[i]);
    }
}

// ---------------- launch -------------------------------------------------------
extern "C" void kernel_launch(void* const* d_in, const int* in_sizes, int n_in,
                              void* d_out, int out_size)
{
    const float* x      = (const float*)d_in[0];
    const float* topo   = (const float*)d_in[1];
    const float* kv_w   = (const float*)d_in[2];
    const float* q_w    = (const float*)d_in[3];
    const float* proj_w = (const float*)d_in[4];
    const float* proj_b = (const float*)d_in[5];
    const int*   is_end = (const int*)d_in[6];

    void *pkv, *pq, *patt, *pxte, *pxe, *pae, *pwkv, *pwq, *pwp;
    cudaGetSymbolAddress(&pkv,  g_kv);
    cudaGetSymbolAddress(&pq,   g_q);
    cudaGetSymbolAddress(&patt, g_att);
    cudaGetSymbolAddress(&pxte, g_xte);
    cudaGetSymbolAddress(&pxe,  g_xe);
    cudaGetSymbolAddress(&pae,  g_ae);
    cudaGetSymbolAddress(&pwkv, g_wkve);
    cudaGetSymbolAddress(&pwq,  g_wqe);
    cudaGetSymbolAddress(&pwp,  g_wpe);

    cudaFuncSetAttribute(attn_kernel, cudaFuncAttributeMaxDynamicSharedMemorySize,
                         ATTN_SMEM_BYTES);
    cudaFuncSetAttribute(gemm_mma_kernel, cudaFuncAttributeMaxDynamicSharedMemorySize,
                         GEMM_SMEM);

    const long act4 = (long)M_ * 512 / 4;
    const long wkv4 = 1024L * 512 / 4;
    const long w4   = 512L * 512 / 4;
    const int  TB   = 256;

    split_dual_kernel<<<(unsigned)((act4 + TB - 1) / TB), TB>>>(
        (const float4*)x, (const float4*)topo, is_end,
        (__nv_bfloat16*)pxe, (__nv_bfloat16*)pxte, act4);
    split_bf16_kernel<<<(unsigned)((wkv4 + TB - 1) / TB), TB>>>(
        (const float4*)kv_w, (__nv_bfloat16*)pwkv, wkv4);
    split_bf16_kernel<<<(unsigned)((w4 + TB - 1) / TB), TB>>>(
        (const float4*)q_w, (__nv_bfloat16*)pwq, w4);
    split_bf16_kernel<<<(unsigned)((w4 + TB - 1) / TB), TB>>>(
        (const float4*)proj_w, (__nv_bfloat16*)pwp, w4);

    gemm_mma_kernel<<<dim3(8, 288), 256, GEMM_SMEM>>>(
        (const __nv_bfloat16*)pxte, (const __nv_bfloat16*)pwkv, nullptr, (float*)pkv, 1024);
    gemm_mma_kernel<<<dim3(4, 288), 256, GEMM_SMEM>>>(
        (const __nv_bfloat16*)pxe, (const __nv_bfloat16*)pwq, nullptr, (float*)pq, 512);
    attn_kernel<<<B_ * 8, 256, ATTN_SMEM_BYTES>>>((float*)pq, (float*)pkv, (float*)patt);
    split_bf16_kernel<<<(unsigned)((act4 + TB - 1) / TB), TB>>>(
        (const float4*)patt, (__nv_bfloat16*)pae, act4);
    gemm_mma_kernel<<<dim3(4, 288), 256, GEMM_SMEM>>>(
        (const __nv_bfloat16*)pae, (const __nv_bfloat16*)pwp, proj_b, (float*)d_out, 512);
}

// round 11
// speedup vs baseline: 1.8641x; 1.2767x over previous
#include <cuda_runtime.h>
#include <cuda_fp16.h>
#include <cstdint>

#define B_   256
#define N_   144
#define M_   (B_ * N_)            // 36864 rows
#define SCALE_ 0.125f             // 64^-0.5

// ---------------- scratch (device globals: allocation-free rule) -------------
__device__ float g_kv [(size_t)M_ * 1024];
__device__ float g_q  [(size_t)M_ * 512];
__device__ float g_att[(size_t)M_ * 512];

// fp16 hi|lo split activations: [rows, 1024] = [hi(512) | lo(512)]
__device__ __half g_xte [(size_t)M_ * 1024];   // x + is_end*topo
__device__ __half g_xe  [(size_t)M_ * 1024];   // x
__device__ __half g_ae  [(size_t)M_ * 1024];   // attention out
// fp16 weights (hi only): [Nc, 512]
__device__ __half g_wkvh[(size_t)1024 * 512];
__device__ __half g_wqh [(size_t)512 * 512];
__device__ __half g_wph [(size_t)512 * 512];

// ---------------- helpers ------------------------------------------------------
__device__ __forceinline__ uint32_t smem_u32(const void* p) {
    uint32_t a;
    asm("{ .reg .u64 t; cvta.to.shared.u64 t, %1; cvt.u32.u64 %0, t; }" : "=r"(a) : "l"(p));
    return a;
}
__device__ __forceinline__ void ldsm_x4(uint32_t& r0, uint32_t& r1, uint32_t& r2,
                                        uint32_t& r3, uint32_t addr) {
    asm volatile("ldmatrix.sync.aligned.m8n8.x4.shared.b16 {%0,%1,%2,%3}, [%4];"
                 : "=r"(r0), "=r"(r1), "=r"(r2), "=r"(r3) : "r"(addr));
}
__device__ __forceinline__ void mma_f16(float* c, uint32_t a0, uint32_t a1,
                                        uint32_t a2, uint32_t a3,
                                        uint32_t b0, uint32_t b1) {
    asm volatile(
        "mma.sync.aligned.m16n8k16.row.col.f32.f16.f16.f32 "
        "{%0,%1,%2,%3}, {%4,%5,%6,%7}, {%8,%9}, {%0,%1,%2,%3};"
        : "+f"(c[0]), "+f"(c[1]), "+f"(c[2]), "+f"(c[3])
        : "r"(a0), "r"(a1), "r"(a2), "r"(a3), "r"(b0), "r"(b1));
}
__device__ __forceinline__ void split1h(float v, __half& h, __half& l) {
    h = __float2half_rn(v);
    l = __float2half_rn(v - __half2float(h));
}
__device__ __forceinline__ void cp16(uint32_t dst, const void* src) {
    asm volatile("cp.async.cg.shared.global [%0], [%1], 16;" :: "r"(dst), "l"(src));
}
// packed f32x2
__device__ __forceinline__ unsigned long long pack2(float lo, float hi) {
    unsigned long long r;
    asm("mov.b64 %0, {%1, %2};" : "=l"(r) : "f"(lo), "f"(hi));
    return r;
}
__device__ __forceinline__ void fma2(unsigned long long& d, unsigned long long a, unsigned long long b) {
    asm("fma.rn.f32x2 %0, %1, %2, %0;" : "+l"(d) : "l"(a), "l"(b));
}
__device__ __forceinline__ float2 unpack2(unsigned long long v) {
    float2 r;
    asm("mov.b64 {%0, %1}, %2;" : "=f"(r.x), "=f"(r.y) : "l"(v));
    return r;
}

// ---------------- fp32 -> fp16 hi/lo split (single stream) --------------------
__global__ __launch_bounds__(256)
void split_h_kernel(const float4* __restrict__ in, __half* __restrict__ out,
                    long total4)
{
    long i = (long)blockIdx.x * blockDim.x + threadIdx.x;
    if (i >= total4) return;
    float4 a = in[i];
    long idx = i * 4;
    long row = idx >> 9;
    int  col = (int)(idx & 511);
    float v[4] = { a.x, a.y, a.z, a.w };
    __half h[4], l[4];
#pragma unroll
    for (int j = 0; j < 4; j++) split1h(v[j], h[j], l[j]);
    __half* base = out + row * 1024 + col;
    *(uint2*)(base)       = *(uint2*)h;
    *(uint2*)(base + 512) = *(uint2*)l;
}

// dual: oxe = split(x), oxte = split(x + f*topo)
__global__ __launch_bounds__(256)
void split_dual_h_kernel(const float4* __restrict__ x, const float4* __restrict__ topo,
                         const int* __restrict__ flag,
                         __half* __restrict__ oxe, __half* __restrict__ oxte,
                         long total4)
{
    long i = (long)blockIdx.x * blockDim.x + threadIdx.x;
    if (i >= total4) return;
    float4 a = x[i];
    float4 tp = topo[i];
    float f = (*flag != 0) ? 1.f : 0.f;
    long idx = i * 4;
    long row = idx >> 9;
    int  col = (int)(idx & 511);
    float v1[4] = { a.x, a.y, a.z, a.w };
    float v2[4] = { a.x + f * tp.x, a.y + f * tp.y, a.z + f * tp.z, a.w + f * tp.w };
    __half h[4], l[4];
#pragma unroll
    for (int j = 0; j < 4; j++) split1h(v1[j], h[j], l[j]);
    __half* b1 = oxe + row * 1024 + col;
    *(uint2*)(b1)       = *(uint2*)h;
    *(uint2*)(b1 + 512) = *(uint2*)l;
#pragma unroll
    for (int j = 0; j < 4; j++) split1h(v2[j], h[j], l[j]);
    __half* b2 = oxte + row * 1024 + col;
    *(uint2*)(b2)       = *(uint2*)h;
    *(uint2*)(b2 + 512) = *(uint2*)l;
}

// weights: plain fp32 -> fp16 conversion [Nc,512] linear
__global__ __launch_bounds__(256)
void tohalf_kernel(const float4* __restrict__ in, __half* __restrict__ out, long total4)
{
    long i = (long)blockIdx.x * blockDim.x + threadIdx.x;
    if (i >= total4) return;
    float4 a = in[i];
    __half h[4] = { __float2half_rn(a.x), __float2half_rn(a.y),
                    __float2half_rn(a.z), __float2half_rn(a.w) };
    *(uint2*)(out + i * 4) = *(uint2*)h;
}

// ---------------- mma.sync fp16 GEMM: 2-pass hi/lo, shared-B -------------------
// C[M x Nc] = A_fp32 @ W^T: A split fp16 hi/lo, W truncated fp16.
// 8 K-chunks of 64: per chunk stage {Ahi, Alo, B} once; compute Ahi*B then Alo*B.
#define GTILE   18432                     // 128 rows x 144 B
#define GBUF    (3 * GTILE)               // Ahi + Alo + B = 55296
#define GEMM_SMEM (2 * GBUF)              // 110592, double buffered

__global__ __launch_bounds__(256, 2)
void gemm_mma_kernel(const __half* __restrict__ A,
                     const __half* __restrict__ Bw,
                     const float* __restrict__ bias,
                     float* __restrict__ C, int Nc)
{
    extern __shared__ __align__(128) char smem[];
    const uint32_t sbase = smem_u32(smem);

    const int t    = threadIdx.x;
    const int lane = t & 31;
    const int w    = t >> 5;
    const int wm   = w >> 2;
    const int wn   = w & 3;
    const int row0 = blockIdx.y * 128;
    const int col0 = blockIdx.x * 128;

    // ldmatrix lane addresses (tile-relative)
    const uint32_t aOff = (uint32_t)(wm * 64 + (lane & 15)) * 144 + (lane >> 4) * 16;
    const uint32_t bOff = (uint32_t)(wn * 32 + (lane & 7) + ((lane >> 4) & 1) * 8) * 144
                        + ((lane >> 3) & 1) * 16;

    float acc[4][4][4];
#pragma unroll
    for (int mi = 0; mi < 4; mi++)
#pragma unroll
        for (int nj = 0; nj < 4; nj++)
#pragma unroll
            for (int e = 0; e < 4; e++) acc[mi][nj][e] = 0.f;

    // staging map: thread -> row rowT + j*32 (j=0..3), 16B column chunk chT
    const int rowT = t >> 3;
    const int chT  = t & 7;
    const __half* Ag = A  + (size_t)(row0 + rowT) * 1024 + chT * 8;   // [M,1024] hi|lo
    const __half* Bg = Bw + (size_t)(col0 + rowT) * 512 + chT * 8;    // [Nc,512] hi
    const uint32_t stA = sbase + (uint32_t)rowT * 144 + chT * 16;
    const uint32_t stB = stA + 2 * GTILE;

    auto stage = [&](int c, uint32_t bufOff) {
        const int k0 = c * 64;
#pragma unroll
        for (int j = 0; j < 4; j++) {
            cp16(stA + bufOff + j * 32 * 144,         Ag + (size_t)j * 32 * 1024 + k0);       // A-hi
            cp16(stA + bufOff + GTILE + j * 32 * 144, Ag + (size_t)j * 32 * 1024 + 512 + k0); // A-lo
            cp16(stB + bufOff + j * 32 * 144,         Bg + (size_t)j * 32 * 512 + k0);        // B
        }
        asm volatile("cp.async.commit_group;" ::: "memory");
    };

    stage(0, 0);
    for (int c = 0; c < 8; c++) {
        asm volatile("cp.async.wait_group 0;" ::: "memory");
        __syncthreads();
        if (c < 7) stage(c + 1, (uint32_t)((c + 1) & 1) * GBUF);
        const uint32_t bufOff = (uint32_t)(c & 1) * GBUF;

        // 2 passes: (Ahi,B), (Alo,B)
#pragma unroll
        for (int p = 0; p < 2; p++) {
            const uint32_t aT = sbase + bufOff + (uint32_t)p * GTILE + aOff;
            const uint32_t bT = sbase + bufOff + 2 * GTILE + bOff;
#pragma unroll
            for (int ks = 0; ks < 4; ks++) {
                uint32_t ar[4][4], br[2][4];
#pragma unroll
                for (int mi = 0; mi < 4; mi++)
                    ldsm_x4(ar[mi][0], ar[mi][1], ar[mi][2], ar[mi][3],
                            aT + (uint32_t)mi * 16 * 144 + ks * 32);
#pragma unroll
                for (int pj = 0; pj < 2; pj++)
                    ldsm_x4(br[pj][0], br[pj][1], br[pj][2], br[pj][3],
                            bT + (uint32_t)pj * 16 * 144 + ks * 32);
#pragma unroll
                for (int mi = 0; mi < 4; mi++)
#pragma unroll
                    for (int nj = 0; nj < 4; nj++) {
                        const int pj = nj >> 1, hb = (nj & 1) * 2;
                        mma_f16(acc[mi][nj], ar[mi][0], ar[mi][1], ar[mi][2], ar[mi][3],
                                br[pj][hb], br[pj][hb + 1]);
                    }
            }
        }
    }

    const int rbase = row0 + wm * 64 + (lane >> 2);
    const int cbase = col0 + wn * 32 + (lane & 3) * 2;
#pragma unroll
    for (int mi = 0; mi < 4; mi++) {
#pragma unroll
        for (int nj = 0; nj < 4; nj++) {
            const int r  = rbase + mi * 16;
            const int cc = cbase + nj * 8;
            float b0 = 0.f, b1 = 0.f;
            if (bias) { b0 = bias[cc]; b1 = bias[cc + 1]; }
            *(float2*)(C + (size_t)r * Nc + cc) =
                make_float2(acc[mi][nj][0] + b0, acc[mi][nj][1] + b1);
            *(float2*)(C + (size_t)(r + 8) * Nc + cc) =
                make_float2(acc[mi][nj][2] + b0, acc[mi][nj][3] + b1);
        }
    }
}

// ---------------- attention v3 (exact champion version) ------------------------
#define AP   145
#define VP   68
#define QT_OFF 0
#define KT_OFF (64 * AP)
#define V_OFF  (2 * 64 * AP)
#define PT_OFF (2 * 64 * AP + 144 * VP)
#define ATTN_SMEM_FLOATS (2 * 64 * AP + 144 * VP + 144 * AP)
#define ATTN_SMEM_BYTES  (ATTN_SMEM_FLOATS * 4)

__global__ __launch_bounds__(256, 1)
void attn_kernel(const float* __restrict__ q, const float* __restrict__ kv,
                 float* __restrict__ o)
{
    extern __shared__ float sm[];
    float* Qt = sm + QT_OFF;
    float* Kt = sm + KT_OFF;
    float* Vs = sm + V_OFF;
    float* Pt = sm + PT_OFF;
    float* red = Pt;

    const int b = blockIdx.x >> 3;
    const int h = blockIdx.x & 7;
    const int t = threadIdx.x;
    const int ty = t >> 4;
    const int tx = t & 15;

    const float* qb = q  + (size_t)b * 144 * 512  + h * 64;
    const float* kb = kv + (size_t)b * 144 * 1024 + h * 64;
    const float* vb = kb + 512;

    for (int i = t; i < 144 * 64; i += 256) {
        int r = i >> 6, k = i & 63;
        Qt[k * AP + r] = qb[(size_t)r * 512 + k] * SCALE_;
        Kt[k * AP + r] = kb[(size_t)r * 1024 + k];
    }
    for (int i = t; i < 144 * 16; i += 256) {
        int n = i >> 4, cc = (i & 15) << 2;
        *(float4*)(Vs + n * VP + cc) = *(const float4*)(vb + (size_t)n * 1024 + cc);
    }
    __syncthreads();

    unsigned long long acc2[9][4];
    float acc8[9];
#pragma unroll
    for (int i = 0; i < 9; i++) {
#pragma unroll
        for (int jp = 0; jp < 4; jp++) acc2[i][jp] = 0ull;
        acc8[i] = 0.f;
    }

    const float* Qb = Qt + ty * 9;
    const float* Kb = Kt + tx * 9;
#pragma unroll 2
    for (int k = 0; k < 64; k++) {
        float qv[9], kvv[9];
#pragma unroll
        for (int i = 0; i < 9; i++) qv[i]  = Qb[k * AP + i];
#pragma unroll
        for (int j = 0; j < 9; j++) kvv[j] = Kb[k * AP + j];
        unsigned long long kp[4] = { pack2(kvv[0], kvv[1]), pack2(kvv[2], kvv[3]),
                                     pack2(kvv[4], kvv[5]), pack2(kvv[6], kvv[7]) };
#pragma unroll
        for (int i = 0; i < 9; i++) {
            unsigned long long qd = pack2(qv[i], qv[i]);
#pragma unroll
            for (int jp = 0; jp < 4; jp++) fma2(acc2[i][jp], qd, kp[jp]);
            acc8[i] += qv[i] * kvv[8];
        }
    }

    float s[9][9];
#pragma unroll
    for (int i = 0; i < 9; i++) {
#pragma unroll
        for (int jp = 0; jp < 4; jp++) {
            float2 u = unpack2(acc2[i][jp]);
            s[i][2 * jp]     = u.x;
            s[i][2 * jp + 1] = u.y;
        }
        s[i][8] = acc8[i];
    }

#pragma unroll
    for (int i = 0; i < 9; i++) {
        float m = s[i][0];
#pragma unroll
        for (int j = 1; j < 9; j++) m = fmaxf(m, s[i][j]);
        red[(ty * 9 + i) * 17 + tx] = m;
    }
    __syncthreads();
    float mrow[9];
#pragma unroll
    for (int i = 0; i < 9; i++) {
        const float* rr = red + (ty * 9 + i) * 17;
        float m = rr[0];
#pragma unroll
        for (int u = 1; u < 16; u++) m = fmaxf(m, rr[u]);
        mrow[i] = m;
    }
    __syncthreads();
#pragma unroll
    for (int i = 0; i < 9; i++) {
        float sum = 0.f;
#pragma unroll
        for (int j = 0; j < 9; j++) {
            float e = __expf(s[i][j] - mrow[i]);
            s[i][j] = e;
            sum += e;
        }
        red[(ty * 9 + i) * 17 + tx] = sum;
    }
    __syncthreads();
    float inv[9];
#pragma unroll
    for (int i = 0; i < 9; i++) {
        const float* rr = red + (ty * 9 + i) * 17;
        float sum = rr[0];
#pragma unroll
        for (int u = 1; u < 16; u++) sum += rr[u];
        inv[i] = 1.f / sum;
    }
    __syncthreads();

#pragma unroll
    for (int j = 0; j < 9; j++)
#pragma unroll
        for (int i = 0; i < 9; i++)
            Pt[(tx * 9 + j) * AP + (ty * 9 + i)] = s[i][j];
    __syncthreads();

    unsigned long long out2[9][2];
#pragma unroll
    for (int i = 0; i < 9; i++) { out2[i][0] = 0ull; out2[i][1] = 0ull; }

    const float* Pb = Pt + ty * 9;
#pragma unroll 2
    for (int j = 0; j < 144; j++) {
        float pv[9];
#pragma unroll
        for (int i = 0; i < 9; i++) pv[i] = Pb[j * AP + i];
        float4 vv = *(const float4*)(Vs + j * VP + tx * 4);
        unsigned long long v01 = pack2(vv.x, vv.y);
        unsigned long long v23 = pack2(vv.z, vv.w);
#pragma unroll
        for (int i = 0; i < 9; i++) {
            unsigned long long pd = pack2(pv[i], pv[i]);
            fma2(out2[i][0], pd, v01);
            fma2(out2[i][1], pd, v23);
        }
    }

    float* ob = o + (size_t)b * 144 * 512 + h * 64;
#pragma unroll
    for (int i = 0; i < 9; i++) {
        int r = ty * 9 + i;
        float2 o01 = unpack2(out2[i][0]);
        float2 o23 = unpack2(out2[i][1]);
        *(float4*)(ob + (size_t)r * 512 + tx * 4) =
            make_float4(o01.x * inv[i], o01.y * inv[i],
                        o23.x * inv[i], o23.y * inv[i]);
    }
}

// ---------------- launch -------------------------------------------------------
extern "C" void kernel_launch(void* const* d_in, const int* in_sizes, int n_in,
                              void* d_out, int out_size)
{
    const float* x      = (const float*)d_in[0];
    const float* topo   = (const float*)d_in[1];
    const float* kv_w   = (const float*)d_in[2];
    const float* q_w    = (const float*)d_in[3];
    const float* proj_w = (const float*)d_in[4];
    const float* proj_b = (const float*)d_in[5];
    const int*   is_end = (const int*)d_in[6];

    void *pkv, *pq, *patt, *pxte, *pxe, *pae, *pwkv, *pwq, *pwp;
    cudaGetSymbolAddress(&pkv,  g_kv);
    cudaGetSymbolAddress(&pq,   g_q);
    cudaGetSymbolAddress(&patt, g_att);
    cudaGetSymbolAddress(&pxte, g_xte);
    cudaGetSymbolAddress(&pxe,  g_xe);
    cudaGetSymbolAddress(&pae,  g_ae);
    cudaGetSymbolAddress(&pwkv, g_wkvh);
    cudaGetSymbolAddress(&pwq,  g_wqh);
    cudaGetSymbolAddress(&pwp,  g_wph);

    cudaFuncSetAttribute(attn_kernel, cudaFuncAttributeMaxDynamicSharedMemorySize,
                         ATTN_SMEM_BYTES);
    cudaFuncSetAttribute(gemm_mma_kernel, cudaFuncAttributeMaxDynamicSharedMemorySize,
                         GEMM_SMEM);

    const long act4 = (long)M_ * 512 / 4;
    const long wkv4 = 1024L * 512 / 4;
    const long w4   = 512L * 512 / 4;
    const int  TB   = 256;

    split_dual_h_kernel<<<(unsigned)((act4 + TB - 1) / TB), TB>>>(
        (const float4*)x, (const float4*)topo, is_end,
        (__half*)pxe, (__half*)pxte, act4);
    tohalf_kernel<<<(unsigned)((wkv4 + TB - 1) / TB), TB>>>(
        (const float4*)kv_w, (__half*)pwkv, wkv4);
    tohalf_kernel<<<(unsigned)((w4 + TB - 1) / TB), TB>>>(
        (const float4*)q_w, (__half*)pwq, w4);
    tohalf_kernel<<<(unsigned)((w4 + TB - 1) / TB), TB>>>(
        (const float4*)proj_w, (__half*)pwp, w4);

    gemm_mma_kernel<<<dim3(8, 288), 256, GEMM_SMEM>>>(
        (const __half*)pxte, (const __half*)pwkv, nullptr, (float*)pkv, 1024);
    gemm_mma_kernel<<<dim3(4, 288), 256, GEMM_SMEM>>>(
        (const __half*)pxe, (const __half*)pwq, nullptr, (float*)pq, 512);
    attn_kernel<<<B_ * 8, 256, ATTN_SMEM_BYTES>>>((float*)pq, (float*)pkv, (float*)patt);
    split_h_kernel<<<(unsigned)((act4 + TB - 1) / TB), TB>>>(
        (const float4*)patt, (__half*)pae, act4);
    gemm_mma_kernel<<<dim3(4, 288), 256, GEMM_SMEM>>>(
        (const __half*)pae, (const __half*)pwp, proj_b, (float*)d_out, 512);
}

// round 12
// speedup vs baseline: 2.0617x; 1.1060x over previous
#include <cuda_runtime.h>
#include <cuda_fp16.h>
#include <cstdint>

#define B_   256
#define N_   144
#define M_   (B_ * N_)            // 36864 rows
#define SCALE_ 0.125f             // 64^-0.5

// ---------------- scratch (device globals: allocation-free rule) -------------
__device__ float g_kv [(size_t)M_ * 1024];
__device__ float g_q  [(size_t)M_ * 512];
__device__ float g_att[(size_t)M_ * 512];

// fp16 hi|lo split activations: [rows, 1024] = [hi(512) | lo(512)]
__device__ __half g_xte [(size_t)M_ * 1024];   // x + is_end*topo
__device__ __half g_xe  [(size_t)M_ * 1024];   // x
__device__ __half g_ae  [(size_t)M_ * 1024];   // attention out
// fp16 weights (hi only): [Nc, 512]
__device__ __half g_wkvh[(size_t)1024 * 512];
__device__ __half g_wqh [(size_t)512 * 512];
__device__ __half g_wph [(size_t)512 * 512];

// ---------------- helpers ------------------------------------------------------
__device__ __forceinline__ uint32_t smem_u32(const void* p) {
    uint32_t a;
    asm("{ .reg .u64 t; cvta.to.shared.u64 t, %1; cvt.u32.u64 %0, t; }" : "=r"(a) : "l"(p));
    return a;
}
__device__ __forceinline__ void ldsm_x4(uint32_t& r0, uint32_t& r1, uint32_t& r2,
                                        uint32_t& r3, uint32_t addr) {
    asm volatile("ldmatrix.sync.aligned.m8n8.x4.shared.b16 {%0,%1,%2,%3}, [%4];"
                 : "=r"(r0), "=r"(r1), "=r"(r2), "=r"(r3) : "r"(addr));
}
__device__ __forceinline__ void mma_f16(float* c, uint32_t a0, uint32_t a1,
                                        uint32_t a2, uint32_t a3,
                                        uint32_t b0, uint32_t b1) {
    asm volatile(
        "mma.sync.aligned.m16n8k16.row.col.f32.f16.f16.f32 "
        "{%0,%1,%2,%3}, {%4,%5,%6,%7}, {%8,%9}, {%0,%1,%2,%3};"
        : "+f"(c[0]), "+f"(c[1]), "+f"(c[2]), "+f"(c[3])
        : "r"(a0), "r"(a1), "r"(a2), "r"(a3), "r"(b0), "r"(b1));
}
__device__ __forceinline__ void split1h(float v, __half& h, __half& l) {
    h = __float2half_rn(v);
    l = __float2half_rn(v - __half2float(h));
}
__device__ __forceinline__ void cp16(uint32_t dst, const void* src) {
    asm volatile("cp.async.cg.shared.global [%0], [%1], 16;" :: "r"(dst), "l"(src));
}
// packed f32x2
__device__ __forceinline__ unsigned long long pack2(float lo, float hi) {
    unsigned long long r;
    asm("mov.b64 %0, {%1, %2};" : "=l"(r) : "f"(lo), "f"(hi));
    return r;
}
__device__ __forceinline__ void fma2(unsigned long long& d, unsigned long long a, unsigned long long b) {
    asm("fma.rn.f32x2 %0, %1, %2, %0;" : "+l"(d) : "l"(a), "l"(b));
}
__device__ __forceinline__ float2 unpack2(unsigned long long v) {
    float2 r;
    asm("mov.b64 {%0, %1}, %2;" : "=f"(r.x), "=f"(r.y) : "l"(v));
    return r;
}

// ---------------- fp32 -> fp16 hi/lo split (single stream) --------------------
__global__ __launch_bounds__(256)
void split_h_kernel(const float4* __restrict__ in, __half* __restrict__ out,
                    long total4)
{
    long i = (long)blockIdx.x * blockDim.x + threadIdx.x;
    if (i >= total4) return;
    float4 a = in[i];
    long idx = i * 4;
    long row = idx >> 9;
    int  col = (int)(idx & 511);
    float v[4] = { a.x, a.y, a.z, a.w };
    __half h[4], l[4];
#pragma unroll
    for (int j = 0; j < 4; j++) split1h(v[j], h[j], l[j]);
    __half* base = out + row * 1024 + col;
    *(uint2*)(base)       = *(uint2*)h;
    *(uint2*)(base + 512) = *(uint2*)l;
}

// dual: oxe = split(x), oxte = split(x + f*topo)
__global__ __launch_bounds__(256)
void split_dual_h_kernel(const float4* __restrict__ x, const float4* __restrict__ topo,
                         const int* __restrict__ flag,
                         __half* __restrict__ oxe, __half* __restrict__ oxte,
                         long total4)
{
    long i = (long)blockIdx.x * blockDim.x + threadIdx.x;
    if (i >= total4) return;
    float4 a = x[i];
    float4 tp = topo[i];
    float f = (*flag != 0) ? 1.f : 0.f;
    long idx = i * 4;
    long row = idx >> 9;
    int  col = (int)(idx & 511);
    float v1[4] = { a.x, a.y, a.z, a.w };
    float v2[4] = { a.x + f * tp.x, a.y + f * tp.y, a.z + f * tp.z, a.w + f * tp.w };
    __half h[4], l[4];
#pragma unroll
    for (int j = 0; j < 4; j++) split1h(v1[j], h[j], l[j]);
    __half* b1 = oxe + row * 1024 + col;
    *(uint2*)(b1)       = *(uint2*)h;
    *(uint2*)(b1 + 512) = *(uint2*)l;
#pragma unroll
    for (int j = 0; j < 4; j++) split1h(v2[j], h[j], l[j]);
    __half* b2 = oxte + row * 1024 + col;
    *(uint2*)(b2)       = *(uint2*)h;
    *(uint2*)(b2 + 512) = *(uint2*)l;
}

// weights: plain fp32 -> fp16 conversion [Nc,512] linear
__global__ __launch_bounds__(256)
void tohalf_kernel(const float4* __restrict__ in, __half* __restrict__ out, long total4)
{
    long i = (long)blockIdx.x * blockDim.x + threadIdx.x;
    if (i >= total4) return;
    float4 a = in[i];
    __half h[4] = { __float2half_rn(a.x), __float2half_rn(a.y),
                    __float2half_rn(a.z), __float2half_rn(a.w) };
    *(uint2*)(out + i * 4) = *(uint2*)h;
}

// ---------------- mma.sync fp16 GEMM: 1- or 2-pass hi/lo, shared-B -------------
// C[M x Nc] = A_fp32 @ W^T: A split fp16 hi/lo, W truncated fp16.
// Column tiles with col0 < onepass_cols run only the A-hi pass (score-path
// outputs tolerate fp16 truncation); others run Ahi*B + Alo*B.
#define GTILE   18432                     // 128 rows x 144 B
#define GBUF    (3 * GTILE)               // Ahi + Alo + B = 55296
#define GEMM_SMEM (2 * GBUF)              // 110592, double buffered

__global__ __launch_bounds__(256, 2)
void gemm_mma_kernel(const __half* __restrict__ A,
                     const __half* __restrict__ Bw,
                     const float* __restrict__ bias,
                     float* __restrict__ C, int Nc, int onepass_cols)
{
    extern __shared__ __align__(128) char smem[];
    const uint32_t sbase = smem_u32(smem);

    const int t    = threadIdx.x;
    const int lane = t & 31;
    const int w    = t >> 5;
    const int wm   = w >> 2;
    const int wn   = w & 3;
    const int row0 = blockIdx.y * 128;
    const int col0 = blockIdx.x * 128;
    const int npass = (col0 < onepass_cols) ? 1 : 2;

    // ldmatrix lane addresses (tile-relative)
    const uint32_t aOff = (uint32_t)(wm * 64 + (lane & 15)) * 144 + (lane >> 4) * 16;
    const uint32_t bOff = (uint32_t)(wn * 32 + (lane & 7) + ((lane >> 4) & 1) * 8) * 144
                        + ((lane >> 3) & 1) * 16;

    float acc[4][4][4];
#pragma unroll
    for (int mi = 0; mi < 4; mi++)
#pragma unroll
        for (int nj = 0; nj < 4; nj++)
#pragma unroll
            for (int e = 0; e < 4; e++) acc[mi][nj][e] = 0.f;

    // staging map: thread -> row rowT + j*32 (j=0..3), 16B column chunk chT
    const int rowT = t >> 3;
    const int chT  = t & 7;
    const __half* Ag = A  + (size_t)(row0 + rowT) * 1024 + chT * 8;   // [M,1024] hi|lo
    const __half* Bg = Bw + (size_t)(col0 + rowT) * 512 + chT * 8;    // [Nc,512] hi
    const uint32_t stA = sbase + (uint32_t)rowT * 144 + chT * 16;
    const uint32_t stB = stA + 2 * GTILE;

    auto stage = [&](int c, uint32_t bufOff) {
        const int k0 = c * 64;
#pragma unroll
        for (int j = 0; j < 4; j++) {
            cp16(stA + bufOff + j * 32 * 144, Ag + (size_t)j * 32 * 1024 + k0);           // A-hi
            if (npass == 2)
                cp16(stA + bufOff + GTILE + j * 32 * 144,
                     Ag + (size_t)j * 32 * 1024 + 512 + k0);                              // A-lo
            cp16(stB + bufOff + j * 32 * 144, Bg + (size_t)j * 32 * 512 + k0);            // B
        }
        asm volatile("cp.async.commit_group;" ::: "memory");
    };

    stage(0, 0);
    for (int c = 0; c < 8; c++) {
        asm volatile("cp.async.wait_group 0;" ::: "memory");
        __syncthreads();
        if (c < 7) stage(c + 1, (uint32_t)((c + 1) & 1) * GBUF);
        const uint32_t bufOff = (uint32_t)(c & 1) * GBUF;

        // passes: (Ahi,B) [, (Alo,B)]
        for (int p = 0; p < npass; p++) {
            const uint32_t aT = sbase + bufOff + (uint32_t)p * GTILE + aOff;
            const uint32_t bT = sbase + bufOff + 2 * GTILE + bOff;
#pragma unroll
            for (int ks = 0; ks < 4; ks++) {
                uint32_t ar[4][4], br[2][4];
#pragma unroll
                for (int mi = 0; mi < 4; mi++)
                    ldsm_x4(ar[mi][0], ar[mi][1], ar[mi][2], ar[mi][3],
                            aT + (uint32_t)mi * 16 * 144 + ks * 32);
#pragma unroll
                for (int pj = 0; pj < 2; pj++)
                    ldsm_x4(br[pj][0], br[pj][1], br[pj][2], br[pj][3],
                            bT + (uint32_t)pj * 16 * 144 + ks * 32);
#pragma unroll
                for (int mi = 0; mi < 4; mi++)
#pragma unroll
                    for (int nj = 0; nj < 4; nj++) {
                        const int pj = nj >> 1, hb = (nj & 1) * 2;
                        mma_f16(acc[mi][nj], ar[mi][0], ar[mi][1], ar[mi][2], ar[mi][3],
                                br[pj][hb], br[pj][hb + 1]);
                    }
            }
        }
    }

    const int rbase = row0 + wm * 64 + (lane >> 2);
    const int cbase = col0 + wn * 32 + (lane & 3) * 2;
#pragma unroll
    for (int mi = 0; mi < 4; mi++) {
#pragma unroll
        for (int nj = 0; nj < 4; nj++) {
            const int r  = rbase + mi * 16;
            const int cc = cbase + nj * 8;
            float b0 = 0.f, b1 = 0.f;
            if (bias) { b0 = bias[cc]; b1 = bias[cc + 1]; }
            *(float2*)(C + (size_t)r * Nc + cc) =
                make_float2(acc[mi][nj][0] + b0, acc[mi][nj][1] + b1);
            *(float2*)(C + (size_t)(r + 8) * Nc + cc) =
                make_float2(acc[mi][nj][2] + b0, acc[mi][nj][3] + b1);
        }
    }
}

// ---------------- attention v3 (exact champion version) ------------------------
#define AP   145
#define VP   68
#define QT_OFF 0
#define KT_OFF (64 * AP)
#define V_OFF  (2 * 64 * AP)
#define PT_OFF (2 * 64 * AP + 144 * VP)
#define ATTN_SMEM_FLOATS (2 * 64 * AP + 144 * VP + 144 * AP)
#define ATTN_SMEM_BYTES  (ATTN_SMEM_FLOATS * 4)

__global__ __launch_bounds__(256, 1)
void attn_kernel(const float* __restrict__ q, const float* __restrict__ kv,
                 float* __restrict__ o)
{
    extern __shared__ float sm[];
    float* Qt = sm + QT_OFF;
    float* Kt = sm + KT_OFF;
    float* Vs = sm + V_OFF;
    float* Pt = sm + PT_OFF;
    float* red = Pt;

    const int b = blockIdx.x >> 3;
    const int h = blockIdx.x & 7;
    const int t = threadIdx.x;
    const int ty = t >> 4;
    const int tx = t & 15;

    const float* qb = q  + (size_t)b * 144 * 512  + h * 64;
    const float* kb = kv + (size_t)b * 144 * 1024 + h * 64;
    const float* vb = kb + 512;

    for (int i = t; i < 144 * 64; i += 256) {
        int r = i >> 6, k = i & 63;
        Qt[k * AP + r] = qb[(size_t)r * 512 + k] * SCALE_;
        Kt[k * AP + r] = kb[(size_t)r * 1024 + k];
    }
    for (int i = t; i < 144 * 16; i += 256) {
        int n = i >> 4, cc = (i & 15) << 2;
        *(float4*)(Vs + n * VP + cc) = *(const float4*)(vb + (size_t)n * 1024 + cc);
    }
    __syncthreads();

    unsigned long long acc2[9][4];
    float acc8[9];
#pragma unroll
    for (int i = 0; i < 9; i++) {
#pragma unroll
        for (int jp = 0; jp < 4; jp++) acc2[i][jp] = 0ull;
        acc8[i] = 0.f;
    }

    const float* Qb = Qt + ty * 9;
    const float* Kb = Kt + tx * 9;
#pragma unroll 2
    for (int k = 0; k < 64; k++) {
        float qv[9], kvv[9];
#pragma unroll
        for (int i = 0; i < 9; i++) qv[i]  = Qb[k * AP + i];
#pragma unroll
        for (int j = 0; j < 9; j++) kvv[j] = Kb[k * AP + j];
        unsigned long long kp[4] = { pack2(kvv[0], kvv[1]), pack2(kvv[2], kvv[3]),
                                     pack2(kvv[4], kvv[5]), pack2(kvv[6], kvv[7]) };
#pragma unroll
        for (int i = 0; i < 9; i++) {
            unsigned long long qd = pack2(qv[i], qv[i]);
#pragma unroll
            for (int jp = 0; jp < 4; jp++) fma2(acc2[i][jp], qd, kp[jp]);
            acc8[i] += qv[i] * kvv[8];
        }
    }

    float s[9][9];
#pragma unroll
    for (int i = 0; i < 9; i++) {
#pragma unroll
        for (int jp = 0; jp < 4; jp++) {
            float2 u = unpack2(acc2[i][jp]);
            s[i][2 * jp]     = u.x;
            s[i][2 * jp + 1] = u.y;
        }
        s[i][8] = acc8[i];
    }

#pragma unroll
    for (int i = 0; i < 9; i++) {
        float m = s[i][0];
#pragma unroll
        for (int j = 1; j < 9; j++) m = fmaxf(m, s[i][j]);
        red[(ty * 9 + i) * 17 + tx] = m;
    }
    __syncthreads();
    float mrow[9];
#pragma unroll
    for (int i = 0; i < 9; i++) {
        const float* rr = red + (ty * 9 + i) * 17;
        float m = rr[0];
#pragma unroll
        for (int u = 1; u < 16; u++) m = fmaxf(m, rr[u]);
        mrow[i] = m;
    }
    __syncthreads();
#pragma unroll
    for (int i = 0; i < 9; i++) {
        float sum = 0.f;
#pragma unroll
        for (int j = 0; j < 9; j++) {
            float e = __expf(s[i][j] - mrow[i]);
            s[i][j] = e;
            sum += e;
        }
        red[(ty * 9 + i) * 17 + tx] = sum;
    }
    __syncthreads();
    float inv[9];
#pragma unroll
    for (int i = 0; i < 9; i++) {
        const float* rr = red + (ty * 9 + i) * 17;
        float sum = rr[0];
#pragma unroll
        for (int u = 1; u < 16; u++) sum += rr[u];
        inv[i] = 1.f / sum;
    }
    __syncthreads();

#pragma unroll
    for (int j = 0; j < 9; j++)
#pragma unroll
        for (int i = 0; i < 9; i++)
            Pt[(tx * 9 + j) * AP + (ty * 9 + i)] = s[i][j];
    __syncthreads();

    unsigned long long out2[9][2];
#pragma unroll
    for (int i = 0; i < 9; i++) { out2[i][0] = 0ull; out2[i][1] = 0ull; }

    const float* Pb = Pt + ty * 9;
#pragma unroll 2
    for (int j = 0; j < 144; j++) {
        float pv[9];
#pragma unroll
        for (int i = 0; i < 9; i++) pv[i] = Pb[j * AP + i];
        float4 vv = *(const float4*)(Vs + j * VP + tx * 4);
        unsigned long long v01 = pack2(vv.x, vv.y);
        unsigned long long v23 = pack2(vv.z, vv.w);
#pragma unroll
        for (int i = 0; i < 9; i++) {
            unsigned long long pd = pack2(pv[i], pv[i]);
            fma2(out2[i][0], pd, v01);
            fma2(out2[i][1], pd, v23);
        }
    }

    float* ob = o + (size_t)b * 144 * 512 + h * 64;
#pragma unroll
    for (int i = 0; i < 9; i++) {
        int r = ty * 9 + i;
        float2 o01 = unpack2(out2[i][0]);
        float2 o23 = unpack2(out2[i][1]);
        *(float4*)(ob + (size_t)r * 512 + tx * 4) =
            make_float4(o01.x * inv[i], o01.y * inv[i],
                        o23.x * inv[i], o23.y * inv[i]);
    }
}

// ---------------- launch -------------------------------------------------------
extern "C" void kernel_launch(void* const* d_in, const int* in_sizes, int n_in,
                              void* d_out, int out_size)
{
    const float* x      = (const float*)d_in[0];
    const float* topo   = (const float*)d_in[1];
    const float* kv_w   = (const float*)d_in[2];
    const float* q_w    = (const float*)d_in[3];
    const float* proj_w = (const float*)d_in[4];
    const float* proj_b = (const float*)d_in[5];
    const int*   is_end = (const int*)d_in[6];

    void *pkv, *pq, *patt, *pxte, *pxe, *pae, *pwkv, *pwq, *pwp;
    cudaGetSymbolAddress(&pkv,  g_kv);
    cudaGetSymbolAddress(&pq,   g_q);
    cudaGetSymbolAddress(&patt, g_att);
    cudaGetSymbolAddress(&pxte, g_xte);
    cudaGetSymbolAddress(&pxe,  g_xe);
    cudaGetSymbolAddress(&pae,  g_ae);
    cudaGetSymbolAddress(&pwkv, g_wkvh);
    cudaGetSymbolAddress(&pwq,  g_wqh);
    cudaGetSymbolAddress(&pwp,  g_wph);

    cudaFuncSetAttribute(attn_kernel, cudaFuncAttributeMaxDynamicSharedMemorySize,
                         ATTN_SMEM_BYTES);
    cudaFuncSetAttribute(gemm_mma_kernel, cudaFuncAttributeMaxDynamicSharedMemorySize,
                         GEMM_SMEM);

    const long act4 = (long)M_ * 512 / 4;
    const long wkv4 = 1024L * 512 / 4;
    const long w4   = 512L * 512 / 4;
    const int  TB   = 256;

    split_dual_h_kernel<<<(unsigned)((act4 + TB - 1) / TB), TB>>>(
        (const float4*)x, (const float4*)topo, is_end,
        (__half*)pxe, (__half*)pxte, act4);
    tohalf_kernel<<<(unsigned)((wkv4 + TB - 1) / TB), TB>>>(
        (const float4*)kv_w, (__half*)pwkv, wkv4);
    tohalf_kernel<<<(unsigned)((w4 + TB - 1) / TB), TB>>>(
        (const float4*)q_w, (__half*)pwq, w4);
    tohalf_kernel<<<(unsigned)((w4 + TB - 1) / TB), TB>>>(
        (const float4*)proj_w, (__half*)pwp, w4);

    // KV: K columns (0..511) single-pass, V columns (512..1023) two-pass
    gemm_mma_kernel<<<dim3(8, 288), 256, GEMM_SMEM>>>(
        (const __half*)pxte, (const __half*)pwkv, nullptr, (float*)pkv, 1024, 512);
    // Q: all columns single-pass (score path)
    gemm_mma_kernel<<<dim3(4, 288), 256, GEMM_SMEM>>>(
        (const __half*)pxe, (const __half*)pwq, nullptr, (float*)pq, 512, 512);
    attn_kernel<<<B_ * 8, 256, ATTN_SMEM_BYTES>>>((float*)pq, (float*)pkv, (float*)patt);
    split_h_kernel<<<(unsigned)((act4 + TB - 1) / TB), TB>>>(
        (const float4*)patt, (__half*)pae, act4);
    // proj: full two-pass (direct output path)
    gemm_mma_kernel<<<dim3(4, 288), 256, GEMM_SMEM>>>(
        (const __half*)pae, (const __half*)pwp, proj_b, (float*)d_out, 512, 0);
}

// round 13
// speedup vs baseline: 2.1894x; 1.0619x over previous
#include <cuda_runtime.h>
#include <cuda_fp16.h>
#include <cstdint>

#define B_   256
#define N_   144
#define M_   (B_ * N_)            // 36864 rows
#define SCALE_ 0.125f             // 64^-0.5

// ---------------- scratch (device globals: allocation-free rule) -------------
__device__ float g_kv [(size_t)M_ * 1024];
__device__ float g_q  [(size_t)M_ * 512];
__device__ float g_att[(size_t)M_ * 512];

__device__ __half g_xte [(size_t)M_ * 1024];   // x + is_end*topo, hi|lo (KV A-operand)
__device__ __half g_xh  [(size_t)M_ * 512];    // x, hi only (Q A-operand)
__device__ __half g_ah  [(size_t)M_ * 512];    // attention out, hi only (proj A-operand)
// fp16 weights (hi only): [Nc, 512]
__device__ __half g_wkvh[(size_t)1024 * 512];
__device__ __half g_wqh [(size_t)512 * 512];
__device__ __half g_wph [(size_t)512 * 512];

// ---------------- helpers ------------------------------------------------------
__device__ __forceinline__ uint32_t smem_u32(const void* p) {
    uint32_t a;
    asm("{ .reg .u64 t; cvta.to.shared.u64 t, %1; cvt.u32.u64 %0, t; }" : "=r"(a) : "l"(p));
    return a;
}
__device__ __forceinline__ void ldsm_x4(uint32_t& r0, uint32_t& r1, uint32_t& r2,
                                        uint32_t& r3, uint32_t addr) {
    asm volatile("ldmatrix.sync.aligned.m8n8.x4.shared.b16 {%0,%1,%2,%3}, [%4];"
                 : "=r"(r0), "=r"(r1), "=r"(r2), "=r"(r3) : "r"(addr));
}
__device__ __forceinline__ void mma_f16(float* c, uint32_t a0, uint32_t a1,
                                        uint32_t a2, uint32_t a3,
                                        uint32_t b0, uint32_t b1) {
    asm volatile(
        "mma.sync.aligned.m16n8k16.row.col.f32.f16.f16.f32 "
        "{%0,%1,%2,%3}, {%4,%5,%6,%7}, {%8,%9}, {%0,%1,%2,%3};"
        : "+f"(c[0]), "+f"(c[1]), "+f"(c[2]), "+f"(c[3])
        : "r"(a0), "r"(a1), "r"(a2), "r"(a3), "r"(b0), "r"(b1));
}
__device__ __forceinline__ void split1h(float v, __half& h, __half& l) {
    h = __float2half_rn(v);
    l = __float2half_rn(v - __half2float(h));
}
__device__ __forceinline__ void cp16(uint32_t dst, const void* src) {
    asm volatile("cp.async.cg.shared.global [%0], [%1], 16;" :: "r"(dst), "l"(src));
}
// packed f32x2
__device__ __forceinline__ unsigned long long pack2(float lo, float hi) {
    unsigned long long r;
    asm("mov.b64 %0, {%1, %2};" : "=l"(r) : "f"(lo), "f"(hi));
    return r;
}
__device__ __forceinline__ void fma2(unsigned long long& d, unsigned long long a, unsigned long long b) {
    asm("fma.rn.f32x2 %0, %1, %2, %0;" : "+l"(d) : "l"(a), "l"(b));
}
__device__ __forceinline__ float2 unpack2(unsigned long long v) {
    float2 r;
    asm("mov.b64 {%0, %1}, %2;" : "=f"(r.x), "=f"(r.y) : "l"(v));
    return r;
}

// ---------------- x prep: g_xte = split(x + f*topo) hi|lo; g_xh = fp16(x) ------
__global__ __launch_bounds__(256)
void prep_x_kernel(const float4* __restrict__ x, const float4* __restrict__ topo,
                   const int* __restrict__ flag,
                   __half* __restrict__ oxte, __half* __restrict__ oxh,
                   long total4)
{
    long i = (long)blockIdx.x * blockDim.x + threadIdx.x;
    if (i >= total4) return;
    float4 a = x[i];
    float4 tp = topo[i];
    float f = (*flag != 0) ? 1.f : 0.f;
    long idx = i * 4;
    long row = idx >> 9;
    int  col = (int)(idx & 511);

    // x hi only -> [M,512]
    __half xh[4] = { __float2half_rn(a.x), __float2half_rn(a.y),
                     __float2half_rn(a.z), __float2half_rn(a.w) };
    *(uint2*)(oxh + idx) = *(uint2*)xh;

    // x + f*topo, hi|lo -> [M,1024]
    float v2[4] = { a.x + f * tp.x, a.y + f * tp.y, a.z + f * tp.z, a.w + f * tp.w };
    __half h[4], l[4];
#pragma unroll
    for (int j = 0; j < 4; j++) split1h(v2[j], h[j], l[j]);
    __half* b2 = oxte + row * 1024 + col;
    *(uint2*)(b2)       = *(uint2*)h;
    *(uint2*)(b2 + 512) = *(uint2*)l;
}

// plain fp32 -> fp16 conversion (weights, attention output)
__global__ __launch_bounds__(256)
void tohalf_kernel(const float4* __restrict__ in, __half* __restrict__ out, long total4)
{
    long i = (long)blockIdx.x * blockDim.x + threadIdx.x;
    if (i >= total4) return;
    float4 a = in[i];
    __half h[4] = { __float2half_rn(a.x), __float2half_rn(a.y),
                    __float2half_rn(a.z), __float2half_rn(a.w) };
    *(uint2*)(out + i * 4) = *(uint2*)h;
}

// ---------------- mma.sync fp16 GEMM: 1- or 2-pass hi/lo, shared-B -------------
// C[M x Nc] = A @ W^T (+bias).  A row stride = strideA elements; when a column
// tile runs 2-pass, the A-lo half lives at row offset +512 (requires strideA=1024).
#define GTILE   18432                     // 128 rows x 144 B
#define GBUF    (3 * GTILE)               // Ahi + Alo + B = 55296
#define GEMM_SMEM (2 * GBUF)              // 110592, double buffered

__global__ __launch_bounds__(256, 2)
void gemm_mma_kernel(const __half* __restrict__ A,
                     const __half* __restrict__ Bw,
                     const float* __restrict__ bias,
                     float* __restrict__ C, int Nc, int onepass_cols, int strideA)
{
    extern __shared__ __align__(128) char smem[];
    const uint32_t sbase = smem_u32(smem);

    const int t    = threadIdx.x;
    const int lane = t & 31;
    const int w    = t >> 5;
    const int wm   = w >> 2;
    const int wn   = w & 3;
    const int row0 = blockIdx.y * 128;
    const int col0 = blockIdx.x * 128;
    const int npass = (col0 < onepass_cols) ? 1 : 2;

    const uint32_t aOff = (uint32_t)(wm * 64 + (lane & 15)) * 144 + (lane >> 4) * 16;
    const uint32_t bOff = (uint32_t)(wn * 32 + (lane & 7) + ((lane >> 4) & 1) * 8) * 144
                        + ((lane >> 3) & 1) * 16;

    float acc[4][4][4];
#pragma unroll
    for (int mi = 0; mi < 4; mi++)
#pragma unroll
        for (int nj = 0; nj < 4; nj++)
#pragma unroll
            for (int e = 0; e < 4; e++) acc[mi][nj][e] = 0.f;

    const int rowT = t >> 3;
    const int chT  = t & 7;
    const __half* Ag = A  + (size_t)(row0 + rowT) * strideA + chT * 8;
    const __half* Bg = Bw + (size_t)(col0 + rowT) * 512 + chT * 8;
    const uint32_t stA = sbase + (uint32_t)rowT * 144 + chT * 16;
    const uint32_t stB = stA + 2 * GTILE;

    auto stage = [&](int c, uint32_t bufOff) {
        const int k0 = c * 64;
#pragma unroll
        for (int j = 0; j < 4; j++) {
            cp16(stA + bufOff + j * 32 * 144, Ag + (size_t)j * 32 * strideA + k0);        // A-hi
            if (npass == 2)
                cp16(stA + bufOff + GTILE + j * 32 * 144,
                     Ag + (size_t)j * 32 * strideA + 512 + k0);                           // A-lo
            cp16(stB + bufOff + j * 32 * 144, Bg + (size_t)j * 32 * 512 + k0);            // B
        }
        asm volatile("cp.async.commit_group;" ::: "memory");
    };

    stage(0, 0);
    for (int c = 0; c < 8; c++) {
        asm volatile("cp.async.wait_group 0;" ::: "memory");
        __syncthreads();
        if (c < 7) stage(c + 1, (uint32_t)((c + 1) & 1) * GBUF);
        const uint32_t bufOff = (uint32_t)(c & 1) * GBUF;

        for (int p = 0; p < npass; p++) {
            const uint32_t aT = sbase + bufOff + (uint32_t)p * GTILE + aOff;
            const uint32_t bT = sbase + bufOff + 2 * GTILE + bOff;
#pragma unroll
            for (int ks = 0; ks < 4; ks++) {
                uint32_t ar[4][4], br[2][4];
#pragma unroll
                for (int mi = 0; mi < 4; mi++)
                    ldsm_x4(ar[mi][0], ar[mi][1], ar[mi][2], ar[mi][3],
                            aT + (uint32_t)mi * 16 * 144 + ks * 32);
#pragma unroll
                for (int pj = 0; pj < 2; pj++)
                    ldsm_x4(br[pj][0], br[pj][1], br[pj][2], br[pj][3],
                            bT + (uint32_t)pj * 16 * 144 + ks * 32);
#pragma unroll
                for (int mi = 0; mi < 4; mi++)
#pragma unroll
                    for (int nj = 0; nj < 4; nj++) {
                        const int pj = nj >> 1, hb = (nj & 1) * 2;
                        mma_f16(acc[mi][nj], ar[mi][0], ar[mi][1], ar[mi][2], ar[mi][3],
                                br[pj][hb], br[pj][hb + 1]);
                    }
            }
        }
    }

    const int rbase = row0 + wm * 64 + (lane >> 2);
    const int cbase = col0 + wn * 32 + (lane & 3) * 2;
#pragma unroll
    for (int mi = 0; mi < 4; mi++) {
#pragma unroll
        for (int nj = 0; nj < 4; nj++) {
            const int r  = rbase + mi * 16;
            const int cc = cbase + nj * 8;
            float b0 = 0.f, b1 = 0.f;
            if (bias) { b0 = bias[cc]; b1 = bias[cc + 1]; }
            *(float2*)(C + (size_t)r * Nc + cc) =
                make_float2(acc[mi][nj][0] + b0, acc[mi][nj][1] + b1);
            *(float2*)(C + (size_t)(r + 8) * Nc + cc) =
                make_float2(acc[mi][nj][2] + b0, acc[mi][nj][3] + b1);
        }
    }
}

// ---------------- attention v3 (exact champion version) ------------------------
#define AP   145
#define VP   68
#define QT_OFF 0
#define KT_OFF (64 * AP)
#define V_OFF  (2 * 64 * AP)
#define PT_OFF (2 * 64 * AP + 144 * VP)
#define ATTN_SMEM_FLOATS (2 * 64 * AP + 144 * VP + 144 * AP)
#define ATTN_SMEM_BYTES  (ATTN_SMEM_FLOATS * 4)

__global__ __launch_bounds__(256, 1)
void attn_kernel(const float* __restrict__ q, const float* __restrict__ kv,
                 float* __restrict__ o)
{
    extern __shared__ float sm[];
    float* Qt = sm + QT_OFF;
    float* Kt = sm + KT_OFF;
    float* Vs = sm + V_OFF;
    float* Pt = sm + PT_OFF;
    float* red = Pt;

    const int b = blockIdx.x >> 3;
    const int h = blockIdx.x & 7;
    const int t = threadIdx.x;
    const int ty = t >> 4;
    const int tx = t & 15;

    const float* qb = q  + (size_t)b * 144 * 512  + h * 64;
    const float* kb = kv + (size_t)b * 144 * 1024 + h * 64;
    const float* vb = kb + 512;

    for (int i = t; i < 144 * 64; i += 256) {
        int r = i >> 6, k = i & 63;
        Qt[k * AP + r] = qb[(size_t)r * 512 + k] * SCALE_;
        Kt[k * AP + r] = kb[(size_t)r * 1024 + k];
    }
    for (int i = t; i < 144 * 16; i += 256) {
        int n = i >> 4, cc = (i & 15) << 2;
        *(float4*)(Vs + n * VP + cc) = *(const float4*)(vb + (size_t)n * 1024 + cc);
    }
    __syncthreads();

    unsigned long long acc2[9][4];
    float acc8[9];
#pragma unroll
    for (int i = 0; i < 9; i++) {
#pragma unroll
        for (int jp = 0; jp < 4; jp++) acc2[i][jp] = 0ull;
        acc8[i] = 0.f;
    }

    const float* Qb = Qt + ty * 9;
    const float* Kb = Kt + tx * 9;
#pragma unroll 2
    for (int k = 0; k < 64; k++) {
        float qv[9], kvv[9];
#pragma unroll
        for (int i = 0; i < 9; i++) qv[i]  = Qb[k * AP + i];
#pragma unroll
        for (int j = 0; j < 9; j++) kvv[j] = Kb[k * AP + j];
        unsigned long long kp[4] = { pack2(kvv[0], kvv[1]), pack2(kvv[2], kvv[3]),
                                     pack2(kvv[4], kvv[5]), pack2(kvv[6], kvv[7]) };
#pragma unroll
        for (int i = 0; i < 9; i++) {
            unsigned long long qd = pack2(qv[i], qv[i]);
#pragma unroll
            for (int jp = 0; jp < 4; jp++) fma2(acc2[i][jp], qd, kp[jp]);
            acc8[i] += qv[i] * kvv[8];
        }
    }

    float s[9][9];
#pragma unroll
    for (int i = 0; i < 9; i++) {
#pragma unroll
        for (int jp = 0; jp < 4; jp++) {
            float2 u = unpack2(acc2[i][jp]);
            s[i][2 * jp]     = u.x;
            s[i][2 * jp + 1] = u.y;
        }
        s[i][8] = acc8[i];
    }

#pragma unroll
    for (int i = 0; i < 9; i++) {
        float m = s[i][0];
#pragma unroll
        for (int j = 1; j < 9; j++) m = fmaxf(m, s[i][j]);
        red[(ty * 9 + i) * 17 + tx] = m;
    }
    __syncthreads();
    float mrow[9];
#pragma unroll
    for (int i = 0; i < 9; i++) {
        const float* rr = red + (ty * 9 + i) * 17;
        float m = rr[0];
#pragma unroll
        for (int u = 1; u < 16; u++) m = fmaxf(m, rr[u]);
        mrow[i] = m;
    }
    __syncthreads();
#pragma unroll
    for (int i = 0; i < 9; i++) {
        float sum = 0.f;
#pragma unroll
        for (int j = 0; j < 9; j++) {
            float e = __expf(s[i][j] - mrow[i]);
            s[i][j] = e;
            sum += e;
        }
        red[(ty * 9 + i) * 17 + tx] = sum;
    }
    __syncthreads();
    float inv[9];
#pragma unroll
    for (int i = 0; i < 9; i++) {
        const float* rr = red + (ty * 9 + i) * 17;
        float sum = rr[0];
#pragma unroll
        for (int u = 1; u < 16; u++) sum += rr[u];
        inv[i] = 1.f / sum;
    }
    __syncthreads();

#pragma unroll
    for (int j = 0; j < 9; j++)
#pragma unroll
        for (int i = 0; i < 9; i++)
            Pt[(tx * 9 + j) * AP + (ty * 9 + i)] = s[i][j];
    __syncthreads();

    unsigned long long out2[9][2];
#pragma unroll
    for (int i = 0; i < 9; i++) { out2[i][0] = 0ull; out2[i][1] = 0ull; }

    const float* Pb = Pt + ty * 9;
#pragma unroll 2
    for (int j = 0; j < 144; j++) {
        float pv[9];
#pragma unroll
        for (int i = 0; i < 9; i++) pv[i] = Pb[j * AP + i];
        float4 vv = *(const float4*)(Vs + j * VP + tx * 4);
        unsigned long long v01 = pack2(vv.x, vv.y);
        unsigned long long v23 = pack2(vv.z, vv.w);
#pragma unroll
        for (int i = 0; i < 9; i++) {
            unsigned long long pd = pack2(pv[i], pv[i]);
            fma2(out2[i][0], pd, v01);
            fma2(out2[i][1], pd, v23);
        }
    }

    float* ob = o + (size_t)b * 144 * 512 + h * 64;
#pragma unroll
    for (int i = 0; i < 9; i++) {
        int r = ty * 9 + i;
        float2 o01 = unpack2(out2[i][0]);
        float2 o23 = unpack2(out2[i][1]);
        *(float4*)(ob + (size_t)r * 512 + tx * 4) =
            make_float4(o01.x * inv[i], o01.y * inv[i],
                        o23.x * inv[i], o23.y * inv[i]);
    }
}

// ---------------- launch -------------------------------------------------------
extern "C" void kernel_launch(void* const* d_in, const int* in_sizes, int n_in,
                              void* d_out, int out_size)
{
    const float* x      = (const float*)d_in[0];
    const float* topo   = (const float*)d_in[1];
    const float* kv_w   = (const float*)d_in[2];
    const float* q_w    = (const float*)d_in[3];
    const float* proj_w = (const float*)d_in[4];
    const float* proj_b = (const float*)d_in[5];
    const int*   is_end = (const int*)d_in[6];

    void *pkv, *pq, *patt, *pxte, *pxh, *pah, *pwkv, *pwq, *pwp;
    cudaGetSymbolAddress(&pkv,  g_kv);
    cudaGetSymbolAddress(&pq,   g_q);
    cudaGetSymbolAddress(&patt, g_att);
    cudaGetSymbolAddress(&pxte, g_xte);
    cudaGetSymbolAddress(&pxh,  g_xh);
    cudaGetSymbolAddress(&pah,  g_ah);
    cudaGetSymbolAddress(&pwkv, g_wkvh);
    cudaGetSymbolAddress(&pwq,  g_wqh);
    cudaGetSymbolAddress(&pwp,  g_wph);

    cudaFuncSetAttribute(attn_kernel, cudaFuncAttributeMaxDynamicSharedMemorySize,
                         ATTN_SMEM_BYTES);
    cudaFuncSetAttribute(gemm_mma_kernel, cudaFuncAttributeMaxDynamicSharedMemorySize,
                         GEMM_SMEM);

    const long act4 = (long)M_ * 512 / 4;
    const long wkv4 = 1024L * 512 / 4;
    const long w4   = 512L * 512 / 4;
    const int  TB   = 256;

    prep_x_kernel<<<(unsigned)((act4 + TB - 1) / TB), TB>>>(
        (const float4*)x, (const float4*)topo, is_end,
        (__half*)pxte, (__half*)pxh, act4);
    tohalf_kernel<<<(unsigned)((wkv4 + TB - 1) / TB), TB>>>(
        (const float4*)kv_w, (__half*)pwkv, wkv4);
    tohalf_kernel<<<(unsigned)((w4 + TB - 1) / TB), TB>>>(
        (const float4*)q_w, (__half*)pwq, w4);
    tohalf_kernel<<<(unsigned)((w4 + TB - 1) / TB), TB>>>(
        (const float4*)proj_w, (__half*)pwp, w4);

    // KV: K columns (0..511) single-pass, V columns (512..1023) two-pass
    gemm_mma_kernel<<<dim3(8, 288), 256, GEMM_SMEM>>>(
        (const __half*)pxte, (const __half*)pwkv, nullptr, (float*)pkv, 1024, 512, 1024);
    // Q: all single-pass, A = g_xh [M,512]
    gemm_mma_kernel<<<dim3(4, 288), 256, GEMM_SMEM>>>(
        (const __half*)pxh, (const __half*)pwq, nullptr, (float*)pq, 512, 512, 512);
    attn_kernel<<<B_ * 8, 256, ATTN_SMEM_BYTES>>>((float*)pq, (float*)pkv, (float*)patt);
    tohalf_kernel<<<(unsigned)((act4 + TB - 1) / TB), TB>>>(
        (const float4*)patt, (__half*)pah, act4);
    // proj: all single-pass, A = g_ah [M,512]
    gemm_mma_kernel<<<dim3(4, 288), 256, GEMM_SMEM>>>(
        (const __half*)pah, (const __half*)pwp, proj_b, (float*)d_out, 512, 512, 512);
}

// round 14
// speedup vs baseline: 2.3387x; 1.0682x over previous
#include <cuda_runtime.h>
#include <cuda_fp16.h>
#include <cstdint>

#define B_   256
#define N_   144
#define M_   (B_ * N_)            // 36864 rows
#define SCALE_ 0.125f             // 64^-0.5

// ---------------- scratch (device globals: allocation-free rule) -------------
__device__ float g_kv [(size_t)M_ * 1024];
__device__ float g_q  [(size_t)M_ * 512];
__device__ float g_att[(size_t)M_ * 512];

__device__ __half g_xteh[(size_t)M_ * 512];    // fp16(x + is_end*topo)  (KV A-operand)
__device__ __half g_xh  [(size_t)M_ * 512];    // fp16(x)                (Q A-operand)
__device__ __half g_ah  [(size_t)M_ * 512];    // fp16(attention out)    (proj A-operand)
// fp16 weights: [Nc, 512]
__device__ __half g_wkvh[(size_t)1024 * 512];
__device__ __half g_wqh [(size_t)512 * 512];
__device__ __half g_wph [(size_t)512 * 512];

// ---------------- helpers ------------------------------------------------------
__device__ __forceinline__ uint32_t smem_u32(const void* p) {
    uint32_t a;
    asm("{ .reg .u64 t; cvta.to.shared.u64 t, %1; cvt.u32.u64 %0, t; }" : "=r"(a) : "l"(p));
    return a;
}
__device__ __forceinline__ void ldsm_x4(uint32_t& r0, uint32_t& r1, uint32_t& r2,
                                        uint32_t& r3, uint32_t addr) {
    asm volatile("ldmatrix.sync.aligned.m8n8.x4.shared.b16 {%0,%1,%2,%3}, [%4];"
                 : "=r"(r0), "=r"(r1), "=r"(r2), "=r"(r3) : "r"(addr));
}
__device__ __forceinline__ void mma_f16(float* c, uint32_t a0, uint32_t a1,
                                        uint32_t a2, uint32_t a3,
                                        uint32_t b0, uint32_t b1) {
    asm volatile(
        "mma.sync.aligned.m16n8k16.row.col.f32.f16.f16.f32 "
        "{%0,%1,%2,%3}, {%4,%5,%6,%7}, {%8,%9}, {%0,%1,%2,%3};"
        : "+f"(c[0]), "+f"(c[1]), "+f"(c[2]), "+f"(c[3])
        : "r"(a0), "r"(a1), "r"(a2), "r"(a3), "r"(b0), "r"(b1));
}
__device__ __forceinline__ void cp16(uint32_t dst, const void* src) {
    asm volatile("cp.async.cg.shared.global [%0], [%1], 16;" :: "r"(dst), "l"(src));
}
// packed f32x2
__device__ __forceinline__ unsigned long long pack2(float lo, float hi) {
    unsigned long long r;
    asm("mov.b64 %0, {%1, %2};" : "=l"(r) : "f"(lo), "f"(hi));
    return r;
}
__device__ __forceinline__ void fma2(unsigned long long& d, unsigned long long a, unsigned long long b) {
    asm("fma.rn.f32x2 %0, %1, %2, %0;" : "+l"(d) : "l"(a), "l"(b));
}
__device__ __forceinline__ float2 unpack2(unsigned long long v) {
    float2 r;
    asm("mov.b64 {%0, %1}, %2;" : "=f"(r.x), "=f"(r.y) : "l"(v));
    return r;
}

// ---------------- x prep: g_xteh = fp16(x + f*topo); g_xh = fp16(x) -------------
__global__ __launch_bounds__(256)
void prep_x_kernel(const float4* __restrict__ x, const float4* __restrict__ topo,
                   const int* __restrict__ flag,
                   __half* __restrict__ oxteh, __half* __restrict__ oxh,
                   long total4)
{
    long i = (long)blockIdx.x * blockDim.x + threadIdx.x;
    if (i >= total4) return;
    float4 a = x[i];
    float4 tp = topo[i];
    float f = (*flag != 0) ? 1.f : 0.f;
    long idx = i * 4;

    __half xh[4] = { __float2half_rn(a.x), __float2half_rn(a.y),
                     __float2half_rn(a.z), __float2half_rn(a.w) };
    *(uint2*)(oxh + idx) = *(uint2*)xh;

    __half xt[4] = { __float2half_rn(a.x + f * tp.x), __float2half_rn(a.y + f * tp.y),
                     __float2half_rn(a.z + f * tp.z), __float2half_rn(a.w + f * tp.w) };
    *(uint2*)(oxteh + idx) = *(uint2*)xt;
}

// plain fp32 -> fp16 conversion (weights, attention output)
__global__ __launch_bounds__(256)
void tohalf_kernel(const float4* __restrict__ in, __half* __restrict__ out, long total4)
{
    long i = (long)blockIdx.x * blockDim.x + threadIdx.x;
    if (i >= total4) return;
    float4 a = in[i];
    __half h[4] = { __float2half_rn(a.x), __float2half_rn(a.y),
                    __float2half_rn(a.z), __float2half_rn(a.w) };
    *(uint2*)(out + i * 4) = *(uint2*)h;
}

// ---------------- mma.sync fp16 GEMM, single-pass, cp.async double-buffered -----
// C[M x Nc] = A @ W^T (+bias).  A:[M,512] fp16, W:[Nc,512] fp16.
// 8 K-chunks of 64; stage {A,B} tiles per chunk (R7 pipeline shape).
#define GTILE   18432                     // 128 rows x 144 B
#define GBUF    (2 * GTILE)               // A + B per stage buffer
#define GEMM_SMEM (2 * GBUF)              // 73728, double buffered

__global__ __launch_bounds__(256, 2)
void gemm_mma_kernel(const __half* __restrict__ A,
                     const __half* __restrict__ Bw,
                     const float* __restrict__ bias,
                     float* __restrict__ C, int Nc)
{
    extern __shared__ __align__(128) char smem[];
    const uint32_t sbase = smem_u32(smem);

    const int t    = threadIdx.x;
    const int lane = t & 31;
    const int w    = t >> 5;
    const int wm   = w >> 2;
    const int wn   = w & 3;
    const int row0 = blockIdx.y * 128;
    const int col0 = blockIdx.x * 128;

    const uint32_t aLane = sbase + (uint32_t)(wm * 64 + (lane & 15)) * 144 + (lane >> 4) * 16;
    const uint32_t bLane = sbase + GTILE
                         + (uint32_t)(wn * 32 + (lane & 7) + ((lane >> 4) & 1) * 8) * 144
                         + ((lane >> 3) & 1) * 16;

    float acc[4][4][4];
#pragma unroll
    for (int mi = 0; mi < 4; mi++)
#pragma unroll
        for (int nj = 0; nj < 4; nj++)
#pragma unroll
            for (int e = 0; e < 4; e++) acc[mi][nj][e] = 0.f;

    const int rowT = t >> 3;
    const int chT  = t & 7;
    const __half* Ag = A  + (size_t)(row0 + rowT) * 512 + chT * 8;
    const __half* Bg = Bw + (size_t)(col0 + rowT) * 512 + chT * 8;
    const uint32_t stA = sbase + (uint32_t)rowT * 144 + chT * 16;
    const uint32_t stB = stA + GTILE;

    auto stage = [&](int c, uint32_t bufOff) {
        const int k0 = c * 64;
#pragma unroll
        for (int j = 0; j < 4; j++) {
            cp16(stA + bufOff + j * 32 * 144, Ag + (size_t)j * 32 * 512 + k0);
            cp16(stB + bufOff + j * 32 * 144, Bg + (size_t)j * 32 * 512 + k0);
        }
        asm volatile("cp.async.commit_group;" ::: "memory");
    };

    stage(0, 0);
    for (int c = 0; c < 8; c++) {
        asm volatile("cp.async.wait_group 0;" ::: "memory");
        __syncthreads();
        if (c < 7) stage(c + 1, (uint32_t)((c + 1) & 1) * GBUF);
        const uint32_t bufOff = (uint32_t)(c & 1) * GBUF;

#pragma unroll
        for (int ks = 0; ks < 4; ks++) {
            uint32_t ar[4][4], br[2][4];
#pragma unroll
            for (int mi = 0; mi < 4; mi++)
                ldsm_x4(ar[mi][0], ar[mi][1], ar[mi][2], ar[mi][3],
                        aLane + bufOff + (uint32_t)mi * 16 * 144 + ks * 32);
#pragma unroll
            for (int pj = 0; pj < 2; pj++)
                ldsm_x4(br[pj][0], br[pj][1], br[pj][2], br[pj][3],
                        bLane + bufOff + (uint32_t)pj * 16 * 144 + ks * 32);
#pragma unroll
            for (int mi = 0; mi < 4; mi++)
#pragma unroll
                for (int nj = 0; nj < 4; nj++) {
                    const int pj = nj >> 1, hb = (nj & 1) * 2;
                    mma_f16(acc[mi][nj], ar[mi][0], ar[mi][1], ar[mi][2], ar[mi][3],
                            br[pj][hb], br[pj][hb + 1]);
                }
        }
    }

    const int rbase = row0 + wm * 64 + (lane >> 2);
    const int cbase = col0 + wn * 32 + (lane & 3) * 2;
#pragma unroll
    for (int mi = 0; mi < 4; mi++) {
#pragma unroll
        for (int nj = 0; nj < 4; nj++) {
            const int r  = rbase + mi * 16;
            const int cc = cbase + nj * 8;
            float b0 = 0.f, b1 = 0.f;
            if (bias) { b0 = bias[cc]; b1 = bias[cc + 1]; }
            *(float2*)(C + (size_t)r * Nc + cc) =
                make_float2(acc[mi][nj][0] + b0, acc[mi][nj][1] + b1);
            *(float2*)(C + (size_t)(r + 8) * Nc + cc) =
                make_float2(acc[mi][nj][2] + b0, acc[mi][nj][3] + b1);
        }
    }
}

// ---------------- attention v3 (exact champion version) ------------------------
#define AP   145
#define VP   68
#define QT_OFF 0
#define KT_OFF (64 * AP)
#define V_OFF  (2 * 64 * AP)
#define PT_OFF (2 * 64 * AP + 144 * VP)
#define ATTN_SMEM_FLOATS (2 * 64 * AP + 144 * VP + 144 * AP)
#define ATTN_SMEM_BYTES  (ATTN_SMEM_FLOATS * 4)

__global__ __launch_bounds__(256, 1)
void attn_kernel(const float* __restrict__ q, const float* __restrict__ kv,
                 float* __restrict__ o)
{
    extern __shared__ float sm[];
    float* Qt = sm + QT_OFF;
    float* Kt = sm + KT_OFF;
    float* Vs = sm + V_OFF;
    float* Pt = sm + PT_OFF;
    float* red = Pt;

    const int b = blockIdx.x >> 3;
    const int h = blockIdx.x & 7;
    const int t = threadIdx.x;
    const int ty = t >> 4;
    const int tx = t & 15;

    const float* qb = q  + (size_t)b * 144 * 512  + h * 64;
    const float* kb = kv + (size_t)b * 144 * 1024 + h * 64;
    const float* vb = kb + 512;

    for (int i = t; i < 144 * 64; i += 256) {
        int r = i >> 6, k = i & 63;
        Qt[k * AP + r] = qb[(size_t)r * 512 + k] * SCALE_;
        Kt[k * AP + r] = kb[(size_t)r * 1024 + k];
    }
    for (int i = t; i < 144 * 16; i += 256) {
        int n = i >> 4, cc = (i & 15) << 2;
        *(float4*)(Vs + n * VP + cc) = *(const float4*)(vb + (size_t)n * 1024 + cc);
    }
    __syncthreads();

    unsigned long long acc2[9][4];
    float acc8[9];
#pragma unroll
    for (int i = 0; i < 9; i++) {
#pragma unroll
        for (int jp = 0; jp < 4; jp++) acc2[i][jp] = 0ull;
        acc8[i] = 0.f;
    }

    const float* Qb = Qt + ty * 9;
    const float* Kb = Kt + tx * 9;
#pragma unroll 2
    for (int k = 0; k < 64; k++) {
        float qv[9], kvv[9];
#pragma unroll
        for (int i = 0; i < 9; i++) qv[i]  = Qb[k * AP + i];
#pragma unroll
        for (int j = 0; j < 9; j++) kvv[j] = Kb[k * AP + j];
        unsigned long long kp[4] = { pack2(kvv[0], kvv[1]), pack2(kvv[2], kvv[3]),
                                     pack2(kvv[4], kvv[5]), pack2(kvv[6], kvv[7]) };
#pragma unroll
        for (int i = 0; i < 9; i++) {
            unsigned long long qd = pack2(qv[i], qv[i]);
#pragma unroll
            for (int jp = 0; jp < 4; jp++) fma2(acc2[i][jp], qd, kp[jp]);
            acc8[i] += qv[i] * kvv[8];
        }
    }

    float s[9][9];
#pragma unroll
    for (int i = 0; i < 9; i++) {
#pragma unroll
        for (int jp = 0; jp < 4; jp++) {
            float2 u = unpack2(acc2[i][jp]);
            s[i][2 * jp]     = u.x;
            s[i][2 * jp + 1] = u.y;
        }
        s[i][8] = acc8[i];
    }

#pragma unroll
    for (int i = 0; i < 9; i++) {
        float m = s[i][0];
#pragma unroll
        for (int j = 1; j < 9; j++) m = fmaxf(m, s[i][j]);
        red[(ty * 9 + i) * 17 + tx] = m;
    }
    __syncthreads();
    float mrow[9];
#pragma unroll
    for (int i = 0; i < 9; i++) {
        const float* rr = red + (ty * 9 + i) * 17;
        float m = rr[0];
#pragma unroll
        for (int u = 1; u < 16; u++) m = fmaxf(m, rr[u]);
        mrow[i] = m;
    }
    __syncthreads();
#pragma unroll
    for (int i = 0; i < 9; i++) {
        float sum = 0.f;
#pragma unroll
        for (int j = 0; j < 9; j++) {
            float e = __expf(s[i][j] - mrow[i]);
            s[i][j] = e;
            sum += e;
        }
        red[(ty * 9 + i) * 17 + tx] = sum;
    }
    __syncthreads();
    float inv[9];
#pragma unroll
    for (int i = 0; i < 9; i++) {
        const float* rr = red + (ty * 9 + i) * 17;
        float sum = rr[0];
#pragma unroll
        for (int u = 1; u < 16; u++) sum += rr[u];
        inv[i] = 1.f / sum;
    }
    __syncthreads();

#pragma unroll
    for (int j = 0; j < 9; j++)
#pragma unroll
        for (int i = 0; i < 9; i++)
            Pt[(tx * 9 + j) * AP + (ty * 9 + i)] = s[i][j];
    __syncthreads();

    unsigned long long out2[9][2];
#pragma unroll
    for (int i = 0; i < 9; i++) { out2[i][0] = 0ull; out2[i][1] = 0ull; }

    const float* Pb = Pt + ty * 9;
#pragma unroll 2
    for (int j = 0; j < 144; j++) {
        float pv[9];
#pragma unroll
        for (int i = 0; i < 9; i++) pv[i] = Pb[j * AP + i];
        float4 vv = *(const float4*)(Vs + j * VP + tx * 4);
        unsigned long long v01 = pack2(vv.x, vv.y);
        unsigned long long v23 = pack2(vv.z, vv.w);
#pragma unroll
        for (int i = 0; i < 9; i++) {
            unsigned long long pd = pack2(pv[i], pv[i]);
            fma2(out2[i][0], pd, v01);
            fma2(out2[i][1], pd, v23);
        }
    }

    float* ob = o + (size_t)b * 144 * 512 + h * 64;
#pragma unroll
    for (int i = 0; i < 9; i++) {
        int r = ty * 9 + i;
        float2 o01 = unpack2(out2[i][0]);
        float2 o23 = unpack2(out2[i][1]);
        *(float4*)(ob + (size_t)r * 512 + tx * 4) =
            make_float4(o01.x * inv[i], o01.y * inv[i],
                        o23.x * inv[i], o23.y * inv[i]);
    }
}

// ---------------- launch -------------------------------------------------------
extern "C" void kernel_launch(void* const* d_in, const int* in_sizes, int n_in,
                              void* d_out, int out_size)
{
    const float* x      = (const float*)d_in[0];
    const float* topo   = (const float*)d_in[1];
    const float* kv_w   = (const float*)d_in[2];
    const float* q_w    = (const float*)d_in[3];
    const float* proj_w = (const float*)d_in[4];
    const float* proj_b = (const float*)d_in[5];
    const int*   is_end = (const int*)d_in[6];

    void *pkv, *pq, *patt, *pxteh, *pxh, *pah, *pwkv, *pwq, *pwp;
    cudaGetSymbolAddress(&pkv,   g_kv);
    cudaGetSymbolAddress(&pq,    g_q);
    cudaGetSymbolAddress(&patt,  g_att);
    cudaGetSymbolAddress(&pxteh, g_xteh);
    cudaGetSymbolAddress(&pxh,   g_xh);
    cudaGetSymbolAddress(&pah,   g_ah);
    cudaGetSymbolAddress(&pwkv,  g_wkvh);
    cudaGetSymbolAddress(&pwq,   g_wqh);
    cudaGetSymbolAddress(&pwp,   g_wph);

    cudaFuncSetAttribute(attn_kernel, cudaFuncAttributeMaxDynamicSharedMemorySize,
                         ATTN_SMEM_BYTES);
    cudaFuncSetAttribute(gemm_mma_kernel, cudaFuncAttributeMaxDynamicSharedMemorySize,
                         GEMM_SMEM);

    const long act4 = (long)M_ * 512 / 4;
    const long wkv4 = 1024L * 512 / 4;
    const long w4   = 512L * 512 / 4;
    const int  TB   = 256;

    prep_x_kernel<<<(unsigned)((act4 + TB - 1) / TB), TB>>>(
        (const float4*)x, (const float4*)topo, is_end,
        (__half*)pxteh, (__half*)pxh, act4);
    tohalf_kernel<<<(unsigned)((wkv4 + TB - 1) / TB), TB>>>(
        (const float4*)kv_w, (__half*)pwkv, wkv4);
    tohalf_kernel<<<(unsigned)((w4 + TB - 1) / TB), TB>>>(
        (const float4*)q_w, (__half*)pwq, w4);
    tohalf_kernel<<<(unsigned)((w4 + TB - 1) / TB), TB>>>(
        (const float4*)proj_w, (__half*)pwp, w4);

    // KV = fp16(x+topo) @ kv_w^T   [36864 x 1024]
    gemm_mma_kernel<<<dim3(8, 288), 256, GEMM_SMEM>>>(
        (const __half*)pxteh, (const __half*)pwkv, nullptr, (float*)pkv, 1024);
    // Q = fp16(x) @ q_w^T          [36864 x 512]
    gemm_mma_kernel<<<dim3(4, 288), 256, GEMM_SMEM>>>(
        (const __half*)pxh, (const __half*)pwq, nullptr, (float*)pq, 512);
    attn_kernel<<<B_ * 8, 256, ATTN_SMEM_BYTES>>>((float*)pq, (float*)pkv, (float*)patt);
    tohalf_kernel<<<(unsigned)((act4 + TB - 1) / TB), TB>>>(
        (const float4*)patt, (__half*)pah, act4);
    // out = fp16(att) @ proj_w^T + proj_b
    gemm_mma_kernel<<<dim3(4, 288), 256, GEMM_SMEM>>>(
        (const __half*)pah, (const __half*)pwp, proj_b, (float*)d_out, 512);
}

// round 15
// speedup vs baseline: 2.3570x; 1.0078x over previous
#include <cuda_runtime.h>
#include <cuda_fp16.h>
#include <cstdint>

#define B_   256
#define N_   144
#define M_   (B_ * N_)            // 36864 rows
#define SCALE_ 0.125f             // 64^-0.5

// ---------------- scratch (device globals: allocation-free rule) -------------
__device__ __half g_kvh[(size_t)M_ * 1024];    // KV GEMM out, fp16
__device__ __half g_qh [(size_t)M_ * 512];     // Q  GEMM out, fp16
__device__ float  g_att[(size_t)M_ * 512];     // attention out, fp32

__device__ __half g_xteh[(size_t)M_ * 512];    // fp16(x + is_end*topo)
__device__ __half g_xh  [(size_t)M_ * 512];    // fp16(x)
__device__ __half g_ah  [(size_t)M_ * 512];    // fp16(attention out)
// fp16 weights: [Nc, 512]
__device__ __half g_wkvh[(size_t)1024 * 512];
__device__ __half g_wqh [(size_t)512 * 512];
__device__ __half g_wph [(size_t)512 * 512];

// ---------------- helpers ------------------------------------------------------
__device__ __forceinline__ uint32_t smem_u32(const void* p) {
    uint32_t a;
    asm("{ .reg .u64 t; cvta.to.shared.u64 t, %1; cvt.u32.u64 %0, t; }" : "=r"(a) : "l"(p));
    return a;
}
__device__ __forceinline__ void ldsm_x4(uint32_t& r0, uint32_t& r1, uint32_t& r2,
                                        uint32_t& r3, uint32_t addr) {
    asm volatile("ldmatrix.sync.aligned.m8n8.x4.shared.b16 {%0,%1,%2,%3}, [%4];"
                 : "=r"(r0), "=r"(r1), "=r"(r2), "=r"(r3) : "r"(addr));
}
__device__ __forceinline__ void mma_f16(float* c, uint32_t a0, uint32_t a1,
                                        uint32_t a2, uint32_t a3,
                                        uint32_t b0, uint32_t b1) {
    asm volatile(
        "mma.sync.aligned.m16n8k16.row.col.f32.f16.f16.f32 "
        "{%0,%1,%2,%3}, {%4,%5,%6,%7}, {%8,%9}, {%0,%1,%2,%3};"
        : "+f"(c[0]), "+f"(c[1]), "+f"(c[2]), "+f"(c[3])
        : "r"(a0), "r"(a1), "r"(a2), "r"(a3), "r"(b0), "r"(b1));
}
__device__ __forceinline__ void cp16(uint32_t dst, const void* src) {
    asm volatile("cp.async.cg.shared.global [%0], [%1], 16;" :: "r"(dst), "l"(src));
}
// packed f32x2
__device__ __forceinline__ unsigned long long pack2(float lo, float hi) {
    unsigned long long r;
    asm("mov.b64 %0, {%1, %2};" : "=l"(r) : "f"(lo), "f"(hi));
    return r;
}
__device__ __forceinline__ void fma2(unsigned long long& d, unsigned long long a, unsigned long long b) {
    asm("fma.rn.f32x2 %0, %1, %2, %0;" : "+l"(d) : "l"(a), "l"(b));
}
__device__ __forceinline__ float2 unpack2(unsigned long long v) {
    float2 r;
    asm("mov.b64 {%0, %1}, %2;" : "=f"(r.x), "=f"(r.y) : "l"(v));
    return r;
}

// ---------------- x prep: g_xteh = fp16(x + f*topo); g_xh = fp16(x) -------------
__global__ __launch_bounds__(256)
void prep_x_kernel(const float4* __restrict__ x, const float4* __restrict__ topo,
                   const int* __restrict__ flag,
                   __half* __restrict__ oxteh, __half* __restrict__ oxh,
                   long total4)
{
    long i = (long)blockIdx.x * blockDim.x + threadIdx.x;
    if (i >= total4) return;
    float4 a = x[i];
    float4 tp = topo[i];
    float f = (*flag != 0) ? 1.f : 0.f;
    long idx = i * 4;

    __half xh[4] = { __float2half_rn(a.x), __float2half_rn(a.y),
                     __float2half_rn(a.z), __float2half_rn(a.w) };
    *(uint2*)(oxh + idx) = *(uint2*)xh;

    __half xt[4] = { __float2half_rn(a.x + f * tp.x), __float2half_rn(a.y + f * tp.y),
                     __float2half_rn(a.z + f * tp.z), __float2half_rn(a.w + f * tp.w) };
    *(uint2*)(oxteh + idx) = *(uint2*)xt;
}

// plain fp32 -> fp16 conversion (weights, attention output)
__global__ __launch_bounds__(256)
void tohalf_kernel(const float4* __restrict__ in, __half* __restrict__ out, long total4)
{
    long i = (long)blockIdx.x * blockDim.x + threadIdx.x;
    if (i >= total4) return;
    float4 a = in[i];
    __half h[4] = { __float2half_rn(a.x), __float2half_rn(a.y),
                    __float2half_rn(a.z), __float2half_rn(a.w) };
    *(uint2*)(out + i * 4) = *(uint2*)h;
}

// ---------------- mma.sync fp16 GEMM, single-pass, cp.async double-buffered -----
// C[M x Nc] = A @ W^T (+bias).  HOUT: write fp16 (attention-input path).
#define GTILE   18432                     // 128 rows x 144 B
#define GBUF    (2 * GTILE)               // A + B per stage buffer
#define GEMM_SMEM (2 * GBUF)              // 73728, double buffered

template<bool HOUT>
__global__ __launch_bounds__(256, 2)
void gemm_mma_kernel(const __half* __restrict__ A,
                     const __half* __restrict__ Bw,
                     const float* __restrict__ bias,
                     void* __restrict__ Cv, int Nc)
{
    extern __shared__ __align__(128) char smem[];
    const uint32_t sbase = smem_u32(smem);

    const int t    = threadIdx.x;
    const int lane = t & 31;
    const int w    = t >> 5;
    const int wm   = w >> 2;
    const int wn   = w & 3;
    const int row0 = blockIdx.y * 128;
    const int col0 = blockIdx.x * 128;

    const uint32_t aLane = sbase + (uint32_t)(wm * 64 + (lane & 15)) * 144 + (lane >> 4) * 16;
    const uint32_t bLane = sbase + GTILE
                         + (uint32_t)(wn * 32 + (lane & 7) + ((lane >> 4) & 1) * 8) * 144
                         + ((lane >> 3) & 1) * 16;

    float acc[4][4][4];
#pragma unroll
    for (int mi = 0; mi < 4; mi++)
#pragma unroll
        for (int nj = 0; nj < 4; nj++)
#pragma unroll
            for (int e = 0; e < 4; e++) acc[mi][nj][e] = 0.f;

    const int rowT = t >> 3;
    const int chT  = t & 7;
    const __half* Ag = A  + (size_t)(row0 + rowT) * 512 + chT * 8;
    const __half* Bg = Bw + (size_t)(col0 + rowT) * 512 + chT * 8;
    const uint32_t stA = sbase + (uint32_t)rowT * 144 + chT * 16;
    const uint32_t stB = stA + GTILE;

    auto stage = [&](int c, uint32_t bufOff) {
        const int k0 = c * 64;
#pragma unroll
        for (int j = 0; j < 4; j++) {
            cp16(stA + bufOff + j * 32 * 144, Ag + (size_t)j * 32 * 512 + k0);
            cp16(stB + bufOff + j * 32 * 144, Bg + (size_t)j * 32 * 512 + k0);
        }
        asm volatile("cp.async.commit_group;" ::: "memory");
    };

    stage(0, 0);
    for (int c = 0; c < 8; c++) {
        asm volatile("cp.async.wait_group 0;" ::: "memory");
        __syncthreads();
        if (c < 7) stage(c + 1, (uint32_t)((c + 1) & 1) * GBUF);
        const uint32_t bufOff = (uint32_t)(c & 1) * GBUF;

#pragma unroll
        for (int ks = 0; ks < 4; ks++) {
            uint32_t ar[4][4], br[2][4];
#pragma unroll
            for (int mi = 0; mi < 4; mi++)
                ldsm_x4(ar[mi][0], ar[mi][1], ar[mi][2], ar[mi][3],
                        aLane + bufOff + (uint32_t)mi * 16 * 144 + ks * 32);
#pragma unroll
            for (int pj = 0; pj < 2; pj++)
                ldsm_x4(br[pj][0], br[pj][1], br[pj][2], br[pj][3],
                        bLane + bufOff + (uint32_t)pj * 16 * 144 + ks * 32);
#pragma unroll
            for (int mi = 0; mi < 4; mi++)
#pragma unroll
                for (int nj = 0; nj < 4; nj++) {
                    const int pj = nj >> 1, hb = (nj & 1) * 2;
                    mma_f16(acc[mi][nj], ar[mi][0], ar[mi][1], ar[mi][2], ar[mi][3],
                            br[pj][hb], br[pj][hb + 1]);
                }
        }
    }

    const int rbase = row0 + wm * 64 + (lane >> 2);
    const int cbase = col0 + wn * 32 + (lane & 3) * 2;
#pragma unroll
    for (int mi = 0; mi < 4; mi++) {
#pragma unroll
        for (int nj = 0; nj < 4; nj++) {
            const int r  = rbase + mi * 16;
            const int cc = cbase + nj * 8;
            if (HOUT) {
                __half* C = (__half*)Cv;
                *(__half2*)(C + (size_t)r * Nc + cc) =
                    __floats2half2_rn(acc[mi][nj][0], acc[mi][nj][1]);
                *(__half2*)(C + (size_t)(r + 8) * Nc + cc) =
                    __floats2half2_rn(acc[mi][nj][2], acc[mi][nj][3]);
            } else {
                float* C = (float*)Cv;
                float b0 = 0.f, b1 = 0.f;
                if (bias) { b0 = bias[cc]; b1 = bias[cc + 1]; }
                *(float2*)(C + (size_t)r * Nc + cc) =
                    make_float2(acc[mi][nj][0] + b0, acc[mi][nj][1] + b1);
                *(float2*)(C + (size_t)(r + 8) * Nc + cc) =
                    make_float2(acc[mi][nj][2] + b0, acc[mi][nj][3] + b1);
            }
        }
    }
}

// ---------------- attention v3, fp16 inputs (staging-only change) ---------------
#define AP   145
#define VP   68
#define QT_OFF 0
#define KT_OFF (64 * AP)
#define V_OFF  (2 * 64 * AP)
#define PT_OFF (2 * 64 * AP + 144 * VP)
#define ATTN_SMEM_FLOATS (2 * 64 * AP + 144 * VP + 144 * AP)
#define ATTN_SMEM_BYTES  (ATTN_SMEM_FLOATS * 4)

__global__ __launch_bounds__(256, 1)
void attn_kernel(const __half* __restrict__ q, const __half* __restrict__ kv,
                 float* __restrict__ o)
{
    extern __shared__ float sm[];
    float* Qt = sm + QT_OFF;
    float* Kt = sm + KT_OFF;
    float* Vs = sm + V_OFF;
    float* Pt = sm + PT_OFF;
    float* red = Pt;

    const int b = blockIdx.x >> 3;
    const int h = blockIdx.x & 7;
    const int t = threadIdx.x;
    const int ty = t >> 4;
    const int tx = t & 15;

    const __half* qb = q  + (size_t)b * 144 * 512  + h * 64;
    const __half* kb = kv + (size_t)b * 144 * 1024 + h * 64;
    const __half* vb = kb + 512;

    for (int i = t; i < 144 * 64; i += 256) {
        int r = i >> 6, k = i & 63;
        Qt[k * AP + r] = __half2float(qb[(size_t)r * 512 + k]) * SCALE_;
        Kt[k * AP + r] = __half2float(kb[(size_t)r * 1024 + k]);
    }
    for (int i = t; i < 144 * 16; i += 256) {
        int n = i >> 4, cc = (i & 15) << 2;
        uint2 raw = *(const uint2*)(vb + (size_t)n * 1024 + cc);
        const __half2* hp = (const __half2*)&raw;
        float2 f0 = __half22float2(hp[0]);
        float2 f1 = __half22float2(hp[1]);
        *(float4*)(Vs + n * VP + cc) = make_float4(f0.x, f0.y, f1.x, f1.y);
    }
    __syncthreads();

    unsigned long long acc2[9][4];
    float acc8[9];
#pragma unroll
    for (int i = 0; i < 9; i++) {
#pragma unroll
        for (int jp = 0; jp < 4; jp++) acc2[i][jp] = 0ull;
        acc8[i] = 0.f;
    }

    const float* Qb = Qt + ty * 9;
    const float* Kb = Kt + tx * 9;
#pragma unroll 2
    for (int k = 0; k < 64; k++) {
        float qv[9], kvv[9];
#pragma unroll
        for (int i = 0; i < 9; i++) qv[i]  = Qb[k * AP + i];
#pragma unroll
        for (int j = 0; j < 9; j++) kvv[j] = Kb[k * AP + j];
        unsigned long long kp[4] = { pack2(kvv[0], kvv[1]), pack2(kvv[2], kvv[3]),
                                     pack2(kvv[4], kvv[5]), pack2(kvv[6], kvv[7]) };
#pragma unroll
        for (int i = 0; i < 9; i++) {
            unsigned long long qd = pack2(qv[i], qv[i]);
#pragma unroll
            for (int jp = 0; jp < 4; jp++) fma2(acc2[i][jp], qd, kp[jp]);
            acc8[i] += qv[i] * kvv[8];
        }
    }

    float s[9][9];
#pragma unroll
    for (int i = 0; i < 9; i++) {
#pragma unroll
        for (int jp = 0; jp < 4; jp++) {
            float2 u = unpack2(acc2[i][jp]);
            s[i][2 * jp]     = u.x;
            s[i][2 * jp + 1] = u.y;
        }
        s[i][8] = acc8[i];
    }

#pragma unroll
    for (int i = 0; i < 9; i++) {
        float m = s[i][0];
#pragma unroll
        for (int j = 1; j < 9; j++) m = fmaxf(m, s[i][j]);
        red[(ty * 9 + i) * 17 + tx] = m;
    }
    __syncthreads();
    float mrow[9];
#pragma unroll
    for (int i = 0; i < 9; i++) {
        const float* rr = red + (ty * 9 + i) * 17;
        float m = rr[0];
#pragma unroll
        for (int u = 1; u < 16; u++) m = fmaxf(m, rr[u]);
        mrow[i] = m;
    }
    __syncthreads();
#pragma unroll
    for (int i = 0; i < 9; i++) {
        float sum = 0.f;
#pragma unroll
        for (int j = 0; j < 9; j++) {
            float e = __expf(s[i][j] - mrow[i]);
            s[i][j] = e;
            sum += e;
        }
        red[(ty * 9 + i) * 17 + tx] = sum;
    }
    __syncthreads();
    float inv[9];
#pragma unroll
    for (int i = 0; i < 9; i++) {
        const float* rr = red + (ty * 9 + i) * 17;
        float sum = rr[0];
#pragma unroll
        for (int u = 1; u < 16; u++) sum += rr[u];
        inv[i] = 1.f / sum;
    }
    __syncthreads();

#pragma unroll
    for (int j = 0; j < 9; j++)
#pragma unroll
        for (int i = 0; i < 9; i++)
            Pt[(tx * 9 + j) * AP + (ty * 9 + i)] = s[i][j];
    __syncthreads();

    unsigned long long out2[9][2];
#pragma unroll
    for (int i = 0; i < 9; i++) { out2[i][0] = 0ull; out2[i][1] = 0ull; }

    const float* Pb = Pt + ty * 9;
#pragma unroll 2
    for (int j = 0; j < 144; j++) {
        float pv[9];
#pragma unroll
        for (int i = 0; i < 9; i++) pv[i] = Pb[j * AP + i];
        float4 vv = *(const float4*)(Vs + j * VP + tx * 4);
        unsigned long long v01 = pack2(vv.x, vv.y);
        unsigned long long v23 = pack2(vv.z, vv.w);
#pragma unroll
        for (int i = 0; i < 9; i++) {
            unsigned long long pd = pack2(pv[i], pv[i]);
            fma2(out2[i][0], pd, v01);
            fma2(out2[i][1], pd, v23);
        }
    }

    float* ob = o + (size_t)b * 144 * 512 + h * 64;
#pragma unroll
    for (int i = 0; i < 9; i++) {
        int r = ty * 9 + i;
        float2 o01 = unpack2(out2[i][0]);
        float2 o23 = unpack2(out2[i][1]);
        *(float4*)(ob + (size_t)r * 512 + tx * 4) =
            make_float4(o01.x * inv[i], o01.y * inv[i],
                        o23.x * inv[i], o23.y * inv[i]);
    }
}

// ---------------- launch -------------------------------------------------------
extern "C" void kernel_launch(void* const* d_in, const int* in_sizes, int n_in,
                              void* d_out, int out_size)
{
    const float* x      = (const float*)d_in[0];
    const float* topo   = (const float*)d_in[1];
    const float* kv_w   = (const float*)d_in[2];
    const float* q_w    = (const float*)d_in[3];
    const float* proj_w = (const float*)d_in[4];
    const float* proj_b = (const float*)d_in[5];
    const int*   is_end = (const int*)d_in[6];

    void *pkvh, *pqh, *patt, *pxteh, *pxh, *pah, *pwkv, *pwq, *pwp;
    cudaGetSymbolAddress(&pkvh,  g_kvh);
    cudaGetSymbolAddress(&pqh,   g_qh);
    cudaGetSymbolAddress(&patt,  g_att);
    cudaGetSymbolAddress(&pxteh, g_xteh);
    cudaGetSymbolAddress(&pxh,   g_xh);
    cudaGetSymbolAddress(&pah,   g_ah);
    cudaGetSymbolAddress(&pwkv,  g_wkvh);
    cudaGetSymbolAddress(&pwq,   g_wqh);
    cudaGetSymbolAddress(&pwp,   g_wph);

    cudaFuncSetAttribute(attn_kernel, cudaFuncAttributeMaxDynamicSharedMemorySize,
                         ATTN_SMEM_BYTES);
    cudaFuncSetAttribute(gemm_mma_kernel<true>,
                         cudaFuncAttributeMaxDynamicSharedMemorySize, GEMM_SMEM);
    cudaFuncSetAttribute(gemm_mma_kernel<false>,
                         cudaFuncAttributeMaxDynamicSharedMemorySize, GEMM_SMEM);

    const long act4 = (long)M_ * 512 / 4;
    const long wkv4 = 1024L * 512 / 4;
    const long w4   = 512L * 512 / 4;
    const int  TB   = 256;

    prep_x_kernel<<<(unsigned)((act4 + TB - 1) / TB), TB>>>(
        (const float4*)x, (const float4*)topo, is_end,
        (__half*)pxteh, (__half*)pxh, act4);
    tohalf_kernel<<<(unsigned)((wkv4 + TB - 1) / TB), TB>>>(
        (const float4*)kv_w, (__half*)pwkv, wkv4);
    tohalf_kernel<<<(unsigned)((w4 + TB - 1) / TB), TB>>>(
        (const float4*)q_w, (__half*)pwq, w4);
    tohalf_kernel<<<(unsigned)((w4 + TB - 1) / TB), TB>>>(
        (const float4*)proj_w, (__half*)pwp, w4);

    // KV = fp16(x+topo) @ kv_w^T -> fp16 [36864 x 1024]
    gemm_mma_kernel<true><<<dim3(8, 288), 256, GEMM_SMEM>>>(
        (const __half*)pxteh, (const __half*)pwkv, nullptr, pkvh, 1024);
    // Q = fp16(x) @ q_w^T -> fp16 [36864 x 512]
    gemm_mma_kernel<true><<<dim3(4, 288), 256, GEMM_SMEM>>>(
        (const __half*)pxh, (const __half*)pwq, nullptr, pqh, 512);
    attn_kernel<<<B_ * 8, 256, ATTN_SMEM_BYTES>>>(
        (const __half*)pqh, (const __half*)pkvh, (float*)patt);
    tohalf_kernel<<<(unsigned)((act4 + TB - 1) / TB), TB>>>(
        (const float4*)patt, (__half*)pah, act4);
    // out = fp16(att) @ proj_w^T + proj_b -> fp32 d_out
    gemm_mma_kernel<false><<<dim3(4, 288), 256, GEMM_SMEM>>>(
        (const __half*)pah, (const __half*)pwp, proj_b, d_out, 512);
}

// round 16
// speedup vs baseline: 2.4548x; 1.0415x over previous
#include <cuda_runtime.h>
#include <cuda_fp16.h>
#include <cstdint>

#define B_   256
#define N_   144
#define M_   (B_ * N_)            // 36864 rows
#define SCALE_ 0.125f             // 64^-0.5

// ---------------- scratch (device globals: allocation-free rule) -------------
__device__ __half g_kvh[(size_t)M_ * 1024];    // KV GEMM out, fp16
__device__ __half g_qh [(size_t)M_ * 512];     // Q  GEMM out, fp16
__device__ __half g_ah [(size_t)M_ * 512];     // attention out, fp16 (written by attn)

__device__ __half g_xteh[(size_t)M_ * 512];    // fp16(x + is_end*topo)
__device__ __half g_xh  [(size_t)M_ * 512];    // fp16(x)
// fp16 weights: [Nc, 512]
__device__ __half g_wkvh[(size_t)1024 * 512];
__device__ __half g_wqh [(size_t)512 * 512];
__device__ __half g_wph [(size_t)512 * 512];

// ---------------- helpers ------------------------------------------------------
__device__ __forceinline__ uint32_t smem_u32(const void* p) {
    uint32_t a;
    asm("{ .reg .u64 t; cvta.to.shared.u64 t, %1; cvt.u32.u64 %0, t; }" : "=r"(a) : "l"(p));
    return a;
}
__device__ __forceinline__ void ldsm_x4(uint32_t& r0, uint32_t& r1, uint32_t& r2,
                                        uint32_t& r3, uint32_t addr) {
    asm volatile("ldmatrix.sync.aligned.m8n8.x4.shared.b16 {%0,%1,%2,%3}, [%4];"
                 : "=r"(r0), "=r"(r1), "=r"(r2), "=r"(r3) : "r"(addr));
}
__device__ __forceinline__ void mma_f16(float* c, uint32_t a0, uint32_t a1,
                                        uint32_t a2, uint32_t a3,
                                        uint32_t b0, uint32_t b1) {
    asm volatile(
        "mma.sync.aligned.m16n8k16.row.col.f32.f16.f16.f32 "
        "{%0,%1,%2,%3}, {%4,%5,%6,%7}, {%8,%9}, {%0,%1,%2,%3};"
        : "+f"(c[0]), "+f"(c[1]), "+f"(c[2]), "+f"(c[3])
        : "r"(a0), "r"(a1), "r"(a2), "r"(a3), "r"(b0), "r"(b1));
}
__device__ __forceinline__ void cp16(uint32_t dst, const void* src) {
    asm volatile("cp.async.cg.shared.global [%0], [%1], 16;" :: "r"(dst), "l"(src));
}
// packed f32x2
__device__ __forceinline__ unsigned long long pack2(float lo, float hi) {
    unsigned long long r;
    asm("mov.b64 %0, {%1, %2};" : "=l"(r) : "f"(lo), "f"(hi));
    return r;
}
__device__ __forceinline__ void fma2(unsigned long long& d, unsigned long long a, unsigned long long b) {
    asm("fma.rn.f32x2 %0, %1, %2, %0;" : "+l"(d) : "l"(a), "l"(b));
}
__device__ __forceinline__ float2 unpack2(unsigned long long v) {
    float2 r;
    asm("mov.b64 {%0, %1}, %2;" : "=f"(r.x), "=f"(r.y) : "l"(v));
    return r;
}

// ---------------- x prep: g_xteh = fp16(x + f*topo); g_xh = fp16(x) -------------
__global__ __launch_bounds__(256)
void prep_x_kernel(const float4* __restrict__ x, const float4* __restrict__ topo,
                   const int* __restrict__ flag,
                   __half* __restrict__ oxteh, __half* __restrict__ oxh,
                   long total4)
{
    long i = (long)blockIdx.x * blockDim.x + threadIdx.x;
    if (i >= total4) return;
    float4 a = x[i];
    float4 tp = topo[i];
    float f = (*flag != 0) ? 1.f : 0.f;
    long idx = i * 4;

    __half xh[4] = { __float2half_rn(a.x), __float2half_rn(a.y),
                     __float2half_rn(a.z), __float2half_rn(a.w) };
    *(uint2*)(oxh + idx) = *(uint2*)xh;

    __half xt[4] = { __float2half_rn(a.x + f * tp.x), __float2half_rn(a.y + f * tp.y),
                     __float2half_rn(a.z + f * tp.z), __float2half_rn(a.w + f * tp.w) };
    *(uint2*)(oxteh + idx) = *(uint2*)xt;
}

// all three weight tensors -> fp16 in one launch (block-range dispatch)
#define WKV4 (1024L * 512 / 4)    // 131072 float4
#define WQ4  (512L * 512 / 4)     //  65536
#define WP4  (512L * 512 / 4)     //  65536
#define WTOT4 (WKV4 + WQ4 + WP4)  // 262144

__global__ __launch_bounds__(256)
void prep_w_kernel(const float4* __restrict__ kv_w, const float4* __restrict__ q_w,
                   const float4* __restrict__ proj_w,
                   __half* __restrict__ okv, __half* __restrict__ oq,
                   __half* __restrict__ op)
{
    long i = (long)blockIdx.x * blockDim.x + threadIdx.x;
    if (i >= WTOT4) return;
    const float4* src;
    __half* dst;
    long j;
    if (i < WKV4)            { src = kv_w;   dst = okv; j = i; }
    else if (i < WKV4 + WQ4) { src = q_w;    dst = oq;  j = i - WKV4; }
    else                     { src = proj_w; dst = op;  j = i - WKV4 - WQ4; }
    float4 a = src[j];
    __half h[4] = { __float2half_rn(a.x), __float2half_rn(a.y),
                    __float2half_rn(a.z), __float2half_rn(a.w) };
    *(uint2*)(dst + j * 4) = *(uint2*)h;
}

// ---------------- mma.sync fp16 GEMM, single-pass, cp.async double-buffered -----
#define GTILE   18432                     // 128 rows x 144 B
#define GBUF    (2 * GTILE)
#define GEMM_SMEM (2 * GBUF)              // 73728, double buffered

template<bool HOUT>
__global__ __launch_bounds__(256, 2)
void gemm_mma_kernel(const __half* __restrict__ A,
                     const __half* __restrict__ Bw,
                     const float* __restrict__ bias,
                     void* __restrict__ Cv, int Nc)
{
    extern __shared__ __align__(128) char smem[];
    const uint32_t sbase = smem_u32(smem);

    const int t    = threadIdx.x;
    const int lane = t & 31;
    const int w    = t >> 5;
    const int wm   = w >> 2;
    const int wn   = w & 3;
    const int row0 = blockIdx.y * 128;
    const int col0 = blockIdx.x * 128;

    const uint32_t aLane = sbase + (uint32_t)(wm * 64 + (lane & 15)) * 144 + (lane >> 4) * 16;
    const uint32_t bLane = sbase + GTILE
                         + (uint32_t)(wn * 32 + (lane & 7) + ((lane >> 4) & 1) * 8) * 144
                         + ((lane >> 3) & 1) * 16;

    float acc[4][4][4];
#pragma unroll
    for (int mi = 0; mi < 4; mi++)
#pragma unroll
        for (int nj = 0; nj < 4; nj++)
#pragma unroll
            for (int e = 0; e < 4; e++) acc[mi][nj][e] = 0.f;

    const int rowT = t >> 3;
    const int chT  = t & 7;
    const __half* Ag = A  + (size_t)(row0 + rowT) * 512 + chT * 8;
    const __half* Bg = Bw + (size_t)(col0 + rowT) * 512 + chT * 8;
    const uint32_t stA = sbase + (uint32_t)rowT * 144 + chT * 16;
    const uint32_t stB = stA + GTILE;

    auto stage = [&](int c, uint32_t bufOff) {
        const int k0 = c * 64;
#pragma unroll
        for (int j = 0; j < 4; j++) {
            cp16(stA + bufOff + j * 32 * 144, Ag + (size_t)j * 32 * 512 + k0);
            cp16(stB + bufOff + j * 32 * 144, Bg + (size_t)j * 32 * 512 + k0);
        }
        asm volatile("cp.async.commit_group;" ::: "memory");
    };

    stage(0, 0);
    for (int c = 0; c < 8; c++) {
        asm volatile("cp.async.wait_group 0;" ::: "memory");
        __syncthreads();
        if (c < 7) stage(c + 1, (uint32_t)((c + 1) & 1) * GBUF);
        const uint32_t bufOff = (uint32_t)(c & 1) * GBUF;

#pragma unroll
        for (int ks = 0; ks < 4; ks++) {
            uint32_t ar[4][4], br[2][4];
#pragma unroll
            for (int mi = 0; mi < 4; mi++)
                ldsm_x4(ar[mi][0], ar[mi][1], ar[mi][2], ar[mi][3],
                        aLane + bufOff + (uint32_t)mi * 16 * 144 + ks * 32);
#pragma unroll
            for (int pj = 0; pj < 2; pj++)
                ldsm_x4(br[pj][0], br[pj][1], br[pj][2], br[pj][3],
                        bLane + bufOff + (uint32_t)pj * 16 * 144 + ks * 32);
#pragma unroll
            for (int mi = 0; mi < 4; mi++)
#pragma unroll
                for (int nj = 0; nj < 4; nj++) {
                    const int pj = nj >> 1, hb = (nj & 1) * 2;
                    mma_f16(acc[mi][nj], ar[mi][0], ar[mi][1], ar[mi][2], ar[mi][3],
                            br[pj][hb], br[pj][hb + 1]);
                }
        }
    }

    const int rbase = row0 + wm * 64 + (lane >> 2);
    const int cbase = col0 + wn * 32 + (lane & 3) * 2;
#pragma unroll
    for (int mi = 0; mi < 4; mi++) {
#pragma unroll
        for (int nj = 0; nj < 4; nj++) {
            const int r  = rbase + mi * 16;
            const int cc = cbase + nj * 8;
            if (HOUT) {
                __half* C = (__half*)Cv;
                *(__half2*)(C + (size_t)r * Nc + cc) =
                    __floats2half2_rn(acc[mi][nj][0], acc[mi][nj][1]);
                *(__half2*)(C + (size_t)(r + 8) * Nc + cc) =
                    __floats2half2_rn(acc[mi][nj][2], acc[mi][nj][3]);
            } else {
                float* C = (float*)Cv;
                float b0 = 0.f, b1 = 0.f;
                if (bias) { b0 = bias[cc]; b1 = bias[cc + 1]; }
                *(float2*)(C + (size_t)r * Nc + cc) =
                    make_float2(acc[mi][nj][0] + b0, acc[mi][nj][1] + b1);
                *(float2*)(C + (size_t)(r + 8) * Nc + cc) =
                    make_float2(acc[mi][nj][2] + b0, acc[mi][nj][3] + b1);
            }
        }
    }
}

// ---------------- attention: fp16 in, fp16 out (epilogue convert only) ----------
#define AP   145
#define VP   68
#define QT_OFF 0
#define KT_OFF (64 * AP)
#define V_OFF  (2 * 64 * AP)
#define PT_OFF (2 * 64 * AP + 144 * VP)
#define ATTN_SMEM_FLOATS (2 * 64 * AP + 144 * VP + 144 * AP)
#define ATTN_SMEM_BYTES  (ATTN_SMEM_FLOATS * 4)

__global__ __launch_bounds__(256, 1)
void attn_kernel(const __half* __restrict__ q, const __half* __restrict__ kv,
                 __half* __restrict__ o)
{
    extern __shared__ float sm[];
    float* Qt = sm + QT_OFF;
    float* Kt = sm + KT_OFF;
    float* Vs = sm + V_OFF;
    float* Pt = sm + PT_OFF;
    float* red = Pt;

    const int b = blockIdx.x >> 3;
    const int h = blockIdx.x & 7;
    const int t = threadIdx.x;
    const int ty = t >> 4;
    const int tx = t & 15;

    const __half* qb = q  + (size_t)b * 144 * 512  + h * 64;
    const __half* kb = kv + (size_t)b * 144 * 1024 + h * 64;
    const __half* vb = kb + 512;

    for (int i = t; i < 144 * 64; i += 256) {
        int r = i >> 6, k = i & 63;
        Qt[k * AP + r] = __half2float(qb[(size_t)r * 512 + k]) * SCALE_;
        Kt[k * AP + r] = __half2float(kb[(size_t)r * 1024 + k]);
    }
    for (int i = t; i < 144 * 16; i += 256) {
        int n = i >> 4, cc = (i & 15) << 2;
        uint2 raw = *(const uint2*)(vb + (size_t)n * 1024 + cc);
        const __half2* hp = (const __half2*)&raw;
        float2 f0 = __half22float2(hp[0]);
        float2 f1 = __half22float2(hp[1]);
        *(float4*)(Vs + n * VP + cc) = make_float4(f0.x, f0.y, f1.x, f1.y);
    }
    __syncthreads();

    unsigned long long acc2[9][4];
    float acc8[9];
#pragma unroll
    for (int i = 0; i < 9; i++) {
#pragma unroll
        for (int jp = 0; jp < 4; jp++) acc2[i][jp] = 0ull;
        acc8[i] = 0.f;
    }

    const float* Qb = Qt + ty * 9;
    const float* Kb = Kt + tx * 9;
#pragma unroll 2
    for (int k = 0; k < 64; k++) {
        float qv[9], kvv[9];
#pragma unroll
        for (int i = 0; i < 9; i++) qv[i]  = Qb[k * AP + i];
#pragma unroll
        for (int j = 0; j < 9; j++) kvv[j] = Kb[k * AP + j];
        unsigned long long kp[4] = { pack2(kvv[0], kvv[1]), pack2(kvv[2], kvv[3]),
                                     pack2(kvv[4], kvv[5]), pack2(kvv[6], kvv[7]) };
#pragma unroll
        for (int i = 0; i < 9; i++) {
            unsigned long long qd = pack2(qv[i], qv[i]);
#pragma unroll
            for (int jp = 0; jp < 4; jp++) fma2(acc2[i][jp], qd, kp[jp]);
            acc8[i] += qv[i] * kvv[8];
        }
    }

    float s[9][9];
#pragma unroll
    for (int i = 0; i < 9; i++) {
#pragma unroll
        for (int jp = 0; jp < 4; jp++) {
            float2 u = unpack2(acc2[i][jp]);
            s[i][2 * jp]     = u.x;
            s[i][2 * jp + 1] = u.y;
        }
        s[i][8] = acc8[i];
    }

#pragma unroll
    for (int i = 0; i < 9; i++) {
        float m = s[i][0];
#pragma unroll
        for (int j = 1; j < 9; j++) m = fmaxf(m, s[i][j]);
        red[(ty * 9 + i) * 17 + tx] = m;
    }
    __syncthreads();
    float mrow[9];
#pragma unroll
    for (int i = 0; i < 9; i++) {
        const float* rr = red + (ty * 9 + i) * 17;
        float m = rr[0];
#pragma unroll
        for (int u = 1; u < 16; u++) m = fmaxf(m, rr[u]);
        mrow[i] = m;
    }
    __syncthreads();
#pragma unroll
    for (int i = 0; i < 9; i++) {
        float sum = 0.f;
#pragma unroll
        for (int j = 0; j < 9; j++) {
            float e = __expf(s[i][j] - mrow[i]);
            s[i][j] = e;
            sum += e;
        }
        red[(ty * 9 + i) * 17 + tx] = sum;
    }
    __syncthreads();
    float inv[9];
#pragma unroll
    for (int i = 0; i < 9; i++) {
        const float* rr = red + (ty * 9 + i) * 17;
        float sum = rr[0];
#pragma unroll
        for (int u = 1; u < 16; u++) sum += rr[u];
        inv[i] = 1.f / sum;
    }
    __syncthreads();

#pragma unroll
    for (int j = 0; j < 9; j++)
#pragma unroll
        for (int i = 0; i < 9; i++)
            Pt[(tx * 9 + j) * AP + (ty * 9 + i)] = s[i][j];
    __syncthreads();

    unsigned long long out2[9][2];
#pragma unroll
    for (int i = 0; i < 9; i++) { out2[i][0] = 0ull; out2[i][1] = 0ull; }

    const float* Pb = Pt + ty * 9;
#pragma unroll 2
    for (int j = 0; j < 144; j++) {
        float pv[9];
#pragma unroll
        for (int i = 0; i < 9; i++) pv[i] = Pb[j * AP + i];
        float4 vv = *(const float4*)(Vs + j * VP + tx * 4);
        unsigned long long v01 = pack2(vv.x, vv.y);
        unsigned long long v23 = pack2(vv.z, vv.w);
#pragma unroll
        for (int i = 0; i < 9; i++) {
            unsigned long long pd = pack2(pv[i], pv[i]);
            fma2(out2[i][0], pd, v01);
            fma2(out2[i][1], pd, v23);
        }
    }

    // epilogue: fp16 store (value-identical to fp32 store + later convert)
    __half* ob = o + (size_t)b * 144 * 512 + h * 64 + tx * 4;
#pragma unroll
    for (int i = 0; i < 9; i++) {
        int r = ty * 9 + i;
        float2 o01 = unpack2(out2[i][0]);
        float2 o23 = unpack2(out2[i][1]);
        __half2 h0 = __floats2half2_rn(o01.x * inv[i], o01.y * inv[i]);
        __half2 h1 = __floats2half2_rn(o23.x * inv[i], o23.y * inv[i]);
        uint2 pk;
        pk.x = *(uint32_t*)&h0;
        pk.y = *(uint32_t*)&h1;
        *(uint2*)(ob + (size_t)r * 512) = pk;
    }
}

// ---------------- launch -------------------------------------------------------
extern "C" void kernel_launch(void* const* d_in, const int* in_sizes, int n_in,
                              void* d_out, int out_size)
{
    const float* x      = (const float*)d_in[0];
    const float* topo   = (const float*)d_in[1];
    const float* kv_w   = (const float*)d_in[2];
    const float* q_w    = (const float*)d_in[3];
    const float* proj_w = (const float*)d_in[4];
    const float* proj_b = (const float*)d_in[5];
    const int*   is_end = (const int*)d_in[6];

    void *pkvh, *pqh, *pxteh, *pxh, *pah, *pwkv, *pwq, *pwp;
    cudaGetSymbolAddress(&pkvh,  g_kvh);
    cudaGetSymbolAddress(&pqh,   g_qh);
    cudaGetSymbolAddress(&pxteh, g_xteh);
    cudaGetSymbolAddress(&pxh,   g_xh);
    cudaGetSymbolAddress(&pah,   g_ah);
    cudaGetSymbolAddress(&pwkv,  g_wkvh);
    cudaGetSymbolAddress(&pwq,   g_wqh);
    cudaGetSymbolAddress(&pwp,   g_wph);

    cudaFuncSetAttribute(attn_kernel, cudaFuncAttributeMaxDynamicSharedMemorySize,
                         ATTN_SMEM_BYTES);
    cudaFuncSetAttribute(gemm_mma_kernel<true>,
                         cudaFuncAttributeMaxDynamicSharedMemorySize, GEMM_SMEM);
    cudaFuncSetAttribute(gemm_mma_kernel<false>,
                         cudaFuncAttributeMaxDynamicSharedMemorySize, GEMM_SMEM);

    const long act4 = (long)M_ * 512 / 4;
    const int  TB   = 256;

    prep_x_kernel<<<(unsigned)((act4 + TB - 1) / TB), TB>>>(
        (const float4*)x, (const float4*)topo, is_end,
        (__half*)pxteh, (__half*)pxh, act4);
    prep_w_kernel<<<(unsigned)((WTOT4 + TB - 1) / TB), TB>>>(
        (const float4*)kv_w, (const float4*)q_w, (const float4*)proj_w,
        (__half*)pwkv, (__half*)pwq, (__half*)pwp);

    // KV = fp16(x+topo) @ kv_w^T -> fp16 [36864 x 1024]
    gemm_mma_kernel<true><<<dim3(8, 288), 256, GEMM_SMEM>>>(
        (const __half*)pxteh, (const __half*)pwkv, nullptr, pkvh, 1024);
    // Q = fp16(x) @ q_w^T -> fp16 [36864 x 512]
    gemm_mma_kernel<true><<<dim3(4, 288), 256, GEMM_SMEM>>>(
        (const __half*)pxh, (const __half*)pwq, nullptr, pqh, 512);
    // attention -> fp16 g_ah directly
    attn_kernel<<<B_ * 8, 256, ATTN_SMEM_BYTES>>>(
        (const __half*)pqh, (const __half*)pkvh, (__half*)pah);
    // out = fp16(att) @ proj_w^T + proj_b -> fp32 d_out
    gemm_mma_kernel<false><<<dim3(4, 288), 256, GEMM_SMEM>>>(
        (const __half*)pah, (const __half*)pwp, proj_b, d_out, 512);
}

// round 17
// speedup vs baseline: 4.5599x; 1.8576x over previous
#include <cuda_runtime.h>
#include <cuda_fp16.h>
#include <cstdint>

#define B_   256
#define N_   144
#define M_   (B_ * N_)            // 36864 rows

// ---------------- scratch (device globals: allocation-free rule) -------------
__device__ __half g_kvh[(size_t)M_ * 1024];    // KV GEMM out, fp16
__device__ __half g_qh [(size_t)M_ * 512];     // Q  GEMM out, fp16
__device__ __half g_ah [(size_t)M_ * 512];     // attention out, fp16

__device__ __half g_xteh[(size_t)M_ * 512];    // fp16(x + is_end*topo)
__device__ __half g_xh  [(size_t)M_ * 512];    // fp16(x)
__device__ __half g_wkvh[(size_t)1024 * 512];
__device__ __half g_wqh [(size_t)512 * 512];
__device__ __half g_wph [(size_t)512 * 512];

// ---------------- helpers ------------------------------------------------------
__device__ __forceinline__ uint32_t smem_u32(const void* p) {
    uint32_t a;
    asm("{ .reg .u64 t; cvta.to.shared.u64 t, %1; cvt.u32.u64 %0, t; }" : "=r"(a) : "l"(p));
    return a;
}
__device__ __forceinline__ void ldsm_x4(uint32_t& r0, uint32_t& r1, uint32_t& r2,
                                        uint32_t& r3, uint32_t addr) {
    asm volatile("ldmatrix.sync.aligned.m8n8.x4.shared.b16 {%0,%1,%2,%3}, [%4];"
                 : "=r"(r0), "=r"(r1), "=r"(r2), "=r"(r3) : "r"(addr));
}
__device__ __forceinline__ void mma_f16(float* c, uint32_t a0, uint32_t a1,
                                        uint32_t a2, uint32_t a3,
                                        uint32_t b0, uint32_t b1) {
    asm volatile(
        "mma.sync.aligned.m16n8k16.row.col.f32.f16.f16.f32 "
        "{%0,%1,%2,%3}, {%4,%5,%6,%7}, {%8,%9}, {%0,%1,%2,%3};"
        : "+f"(c[0]), "+f"(c[1]), "+f"(c[2]), "+f"(c[3])
        : "r"(a0), "r"(a1), "r"(a2), "r"(a3), "r"(b0), "r"(b1));
}
__device__ __forceinline__ void cp16(uint32_t dst, const void* src) {
    asm volatile("cp.async.cg.shared.global [%0], [%1], 16;" :: "r"(dst), "l"(src));
}

// ---------------- x prep: g_xteh = fp16(x + f*topo); g_xh = fp16(x) -------------
__global__ __launch_bounds__(256)
void prep_x_kernel(const float4* __restrict__ x, const float4* __restrict__ topo,
                   const int* __restrict__ flag,
                   __half* __restrict__ oxteh, __half* __restrict__ oxh,
                   long total4)
{
    long i = (long)blockIdx.x * blockDim.x + threadIdx.x;
    if (i >= total4) return;
    float4 a = x[i];
    float4 tp = topo[i];
    float f = (*flag != 0) ? 1.f : 0.f;
    long idx = i * 4;

    __half xh[4] = { __float2half_rn(a.x), __float2half_rn(a.y),
                     __float2half_rn(a.z), __float2half_rn(a.w) };
    *(uint2*)(oxh + idx) = *(uint2*)xh;

    __half xt[4] = { __float2half_rn(a.x + f * tp.x), __float2half_rn(a.y + f * tp.y),
                     __float2half_rn(a.z + f * tp.z), __float2half_rn(a.w + f * tp.w) };
    *(uint2*)(oxteh + idx) = *(uint2*)xt;
}

// all three weight tensors -> fp16 in one launch
#define WKV4 (1024L * 512 / 4)
#define WQ4  (512L * 512 / 4)
#define WP4  (512L * 512 / 4)
#define WTOT4 (WKV4 + WQ4 + WP4)

__global__ __launch_bounds__(256)
void prep_w_kernel(const float4* __restrict__ kv_w, const float4* __restrict__ q_w,
                   const float4* __restrict__ proj_w,
                   __half* __restrict__ okv, __half* __restrict__ oq,
                   __half* __restrict__ op)
{
    long i = (long)blockIdx.x * blockDim.x + threadIdx.x;
    if (i >= WTOT4) return;
    const float4* src;
    __half* dst;
    long j;
    if (i < WKV4)            { src = kv_w;   dst = okv; j = i; }
    else if (i < WKV4 + WQ4) { src = q_w;    dst = oq;  j = i - WKV4; }
    else                     { src = proj_w; dst = op;  j = i - WKV4 - WQ4; }
    float4 a = src[j];
    __half h[4] = { __float2half_rn(a.x), __float2half_rn(a.y),
                    __float2half_rn(a.z), __float2half_rn(a.w) };
    *(uint2*)(dst + j * 4) = *(uint2*)h;
}

// ---------------- mma.sync fp16 GEMM (champion version) -------------------------
#define GTILE   18432
#define GBUF    (2 * GTILE)
#define GEMM_SMEM (2 * GBUF)

template<bool HOUT>
__global__ __launch_bounds__(256, 2)
void gemm_mma_kernel(const __half* __restrict__ A,
                     const __half* __restrict__ Bw,
                     const float* __restrict__ bias,
                     void* __restrict__ Cv, int Nc)
{
    extern __shared__ __align__(128) char smem[];
    const uint32_t sbase = smem_u32(smem);

    const int t    = threadIdx.x;
    const int lane = t & 31;
    const int w    = t >> 5;
    const int wm   = w >> 2;
    const int wn   = w & 3;
    const int row0 = blockIdx.y * 128;
    const int col0 = blockIdx.x * 128;

    const uint32_t aLane = sbase + (uint32_t)(wm * 64 + (lane & 15)) * 144 + (lane >> 4) * 16;
    const uint32_t bLane = sbase + GTILE
                         + (uint32_t)(wn * 32 + (lane & 7) + ((lane >> 4) & 1) * 8) * 144
                         + ((lane >> 3) & 1) * 16;

    float acc[4][4][4];
#pragma unroll
    for (int mi = 0; mi < 4; mi++)
#pragma unroll
        for (int nj = 0; nj < 4; nj++)
#pragma unroll
            for (int e = 0; e < 4; e++) acc[mi][nj][e] = 0.f;

    const int rowT = t >> 3;
    const int chT  = t & 7;
    const __half* Ag = A  + (size_t)(row0 + rowT) * 512 + chT * 8;
    const __half* Bg = Bw + (size_t)(col0 + rowT) * 512 + chT * 8;
    const uint32_t stA = sbase + (uint32_t)rowT * 144 + chT * 16;
    const uint32_t stB = stA + GTILE;

    auto stage = [&](int c, uint32_t bufOff) {
        const int k0 = c * 64;
#pragma unroll
        for (int j = 0; j < 4; j++) {
            cp16(stA + bufOff + j * 32 * 144, Ag + (size_t)j * 32 * 512 + k0);
            cp16(stB + bufOff + j * 32 * 144, Bg + (size_t)j * 32 * 512 + k0);
        }
        asm volatile("cp.async.commit_group;" ::: "memory");
    };

    stage(0, 0);
    for (int c = 0; c < 8; c++) {
        asm volatile("cp.async.wait_group 0;" ::: "memory");
        __syncthreads();
        if (c < 7) stage(c + 1, (uint32_t)((c + 1) & 1) * GBUF);
        const uint32_t bufOff = (uint32_t)(c & 1) * GBUF;

#pragma unroll
        for (int ks = 0; ks < 4; ks++) {
            uint32_t ar[4][4], br[2][4];
#pragma unroll
            for (int mi = 0; mi < 4; mi++)
                ldsm_x4(ar[mi][0], ar[mi][1], ar[mi][2], ar[mi][3],
                        aLane + bufOff + (uint32_t)mi * 16 * 144 + ks * 32);
#pragma unroll
            for (int pj = 0; pj < 2; pj++)
                ldsm_x4(br[pj][0], br[pj][1], br[pj][2], br[pj][3],
                        bLane + bufOff + (uint32_t)pj * 16 * 144 + ks * 32);
#pragma unroll
            for (int mi = 0; mi < 4; mi++)
#pragma unroll
                for (int nj = 0; nj < 4; nj++) {
                    const int pj = nj >> 1, hb = (nj & 1) * 2;
                    mma_f16(acc[mi][nj], ar[mi][0], ar[mi][1], ar[mi][2], ar[mi][3],
                            br[pj][hb], br[pj][hb + 1]);
                }
        }
    }

    const int rbase = row0 + wm * 64 + (lane >> 2);
    const int cbase = col0 + wn * 32 + (lane & 3) * 2;
#pragma unroll
    for (int mi = 0; mi < 4; mi++) {
#pragma unroll
        for (int nj = 0; nj < 4; nj++) {
            const int r  = rbase + mi * 16;
            const int cc = cbase + nj * 8;
            if (HOUT) {
                __half* C = (__half*)Cv;
                *(__half2*)(C + (size_t)r * Nc + cc) =
                    __floats2half2_rn(acc[mi][nj][0], acc[mi][nj][1]);
                *(__half2*)(C + (size_t)(r + 8) * Nc + cc) =
                    __floats2half2_rn(acc[mi][nj][2], acc[mi][nj][3]);
            } else {
                float* C = (float*)Cv;
                float b0 = 0.f, b1 = 0.f;
                if (bias) { b0 = bias[cc]; b1 = bias[cc + 1]; }
                *(float2*)(C + (size_t)r * Nc + cc) =
                    make_float2(acc[mi][nj][0] + b0, acc[mi][nj][1] + b1);
                *(float2*)(C + (size_t)(r + 8) * Nc + cc) =
                    make_float2(acc[mi][nj][2] + b0, acc[mi][nj][3] + b1);
            }
        }
    }
}

// ---------------- attention v4: tensor-core QK + PV ------------------------------
// One CTA per (b,h), 288 threads = 9 warps, warp owns 16 S-rows.
// S = (Q*0.125) @ K^T via mma (S in registers), softmax on fragment layout,
// P -> half2 in registers (C-layout == A-layout), O = P @ V via mma (V^T in smem).
#define QS_OFF  0                            // [144][72] half, pitch 144 B
#define KS_OFF  (144 * 72)                   // [144][72]
#define VT_OFF  (2 * 144 * 72)               // V^T [64][152], pitch 304 B
#define ATTN_SMEM_HALVES (2 * 144 * 72 + 64 * 152)
#define ATTN_SMEM_BYTES  (ATTN_SMEM_HALVES * 2)   // 60928

__global__ __launch_bounds__(288)
void attn_kernel(const __half* __restrict__ q, const __half* __restrict__ kv,
                 __half* __restrict__ o)
{
    extern __shared__ __align__(128) __half sh[];
    __half* Qs = sh + QS_OFF;
    __half* Ks = sh + KS_OFF;
    __half* VT = sh + VT_OFF;
    const uint32_t sbase = smem_u32(sh);

    const int b = blockIdx.x >> 3;
    const int h = blockIdx.x & 7;
    const int t = threadIdx.x;
    const int warp = t >> 5;
    const int lane = t & 31;
    const int wrow = warp * 16;

    const __half* qb = q  + (size_t)b * 144 * 512  + h * 64;
    const __half* kb = kv + (size_t)b * 144 * 1024 + h * 64;
    const __half* vb = kb + 512;

    // ---- stage Q (x0.125, exact), K, V^T ----
    const __half2 s2 = __floats2half2_rn(0.125f, 0.125f);
    for (int it = t; it < 144 * 8; it += 288) {
        int r = it >> 3, ch = it & 7;
        uint4 raw = *(const uint4*)(qb + (size_t)r * 512 + ch * 8);
        __half2* hp = (__half2*)&raw;
#pragma unroll
        for (int u = 0; u < 4; u++) hp[u] = __hmul2(hp[u], s2);
        *(uint4*)(Qs + r * 72 + ch * 8) = raw;

        uint4 kraw = *(const uint4*)(kb + (size_t)r * 1024 + ch * 8);
        *(uint4*)(Ks + r * 72 + ch * 8) = kraw;

        uint4 vraw = *(const uint4*)(vb + (size_t)r * 1024 + ch * 8);
        const __half* vh = (const __half*)&vraw;
#pragma unroll
        for (int u = 0; u < 8; u++) VT[(ch * 8 + u) * 152 + r] = vh[u];
    }
    __syncthreads();

    // ---- QK: S[16 x 144] per warp, fragment accumulate ----
    float sacc[18][4];
#pragma unroll
    for (int nt = 0; nt < 18; nt++)
#pragma unroll
        for (int e = 0; e < 4; e++) sacc[nt][e] = 0.f;

    const uint32_t aAddr = sbase + (uint32_t)(wrow + (lane & 15)) * 144 + (lane >> 4) * 16;
    const uint32_t kOff  = sbase + KS_OFF * 2
                         + (uint32_t)((lane & 7) + ((lane >> 4) & 1) * 8) * 144
                         + ((lane >> 3) & 1) * 16;
#pragma unroll
    for (int ks = 0; ks < 4; ks++) {
        uint32_t a0, a1, a2, a3;
        ldsm_x4(a0, a1, a2, a3, aAddr + ks * 32);
#pragma unroll
        for (int jb = 0; jb < 9; jb++) {
            uint32_t br[4];
            ldsm_x4(br[0], br[1], br[2], br[3], kOff + (uint32_t)jb * 16 * 144 + ks * 32);
            mma_f16(sacc[2 * jb],     a0, a1, a2, a3, br[0], br[1]);
            mma_f16(sacc[2 * jb + 1], a0, a1, a2, a3, br[2], br[3]);
        }
    }

    // ---- softmax on fragment layout (rows g = lane>>2 and g+8) ----
    float mx0 = -1e30f, mx1 = -1e30f;
#pragma unroll
    for (int nt = 0; nt < 18; nt++) {
        mx0 = fmaxf(mx0, fmaxf(sacc[nt][0], sacc[nt][1]));
        mx1 = fmaxf(mx1, fmaxf(sacc[nt][2], sacc[nt][3]));
    }
    mx0 = fmaxf(mx0, __shfl_xor_sync(0xffffffffu, mx0, 1));
    mx0 = fmaxf(mx0, __shfl_xor_sync(0xffffffffu, mx0, 2));
    mx1 = fmaxf(mx1, __shfl_xor_sync(0xffffffffu, mx1, 1));
    mx1 = fmaxf(mx1, __shfl_xor_sync(0xffffffffu, mx1, 2));

    uint32_t ph[18][2];
    float sum0 = 0.f, sum1 = 0.f;
#pragma unroll
    for (int nt = 0; nt < 18; nt++) {
        float e0 = __expf(sacc[nt][0] - mx0);
        float e1 = __expf(sacc[nt][1] - mx0);
        float e2 = __expf(sacc[nt][2] - mx1);
        float e3 = __expf(sacc[nt][3] - mx1);
        sum0 += e0 + e1;
        sum1 += e2 + e3;
        __half2 p0 = __floats2half2_rn(e0, e1);
        __half2 p1 = __floats2half2_rn(e2, e3);
        ph[nt][0] = *(uint32_t*)&p0;
        ph[nt][1] = *(uint32_t*)&p1;
    }
    sum0 += __shfl_xor_sync(0xffffffffu, sum0, 1);
    sum0 += __shfl_xor_sync(0xffffffffu, sum0, 2);
    sum1 += __shfl_xor_sync(0xffffffffu, sum1, 1);
    sum1 += __shfl_xor_sync(0xffffffffu, sum1, 2);
    const float inv0 = 1.f / sum0;
    const float inv1 = 1.f / sum1;

    // ---- PV: O[16 x 64] per warp; A = P fragments (registers), B = V^T smem ----
    float oacc[8][4];
#pragma unroll
    for (int dt = 0; dt < 8; dt++)
#pragma unroll
        for (int e = 0; e < 4; e++) oacc[dt][e] = 0.f;

    const uint32_t vOff = sbase + VT_OFF * 2
                        + (uint32_t)((lane & 7) + ((lane >> 4) & 1) * 8) * 304
                        + ((lane >> 3) & 1) * 16;
#pragma unroll
    for (int ks = 0; ks < 9; ks++) {
        const uint32_t pa0 = ph[2 * ks][0];
        const uint32_t pa1 = ph[2 * ks][1];
        const uint32_t pa2 = ph[2 * ks + 1][0];
        const uint32_t pa3 = ph[2 * ks + 1][1];
#pragma unroll
        for (int db = 0; db < 4; db++) {
            uint32_t br[4];
            ldsm_x4(br[0], br[1], br[2], br[3], vOff + (uint32_t)db * 16 * 304 + ks * 32);
            mma_f16(oacc[2 * db],     pa0, pa1, pa2, pa3, br[0], br[1]);
            mma_f16(oacc[2 * db + 1], pa0, pa1, pa2, pa3, br[2], br[3]);
        }
    }

    // ---- epilogue: x 1/sum, fp16 store ----
    const int g  = lane >> 2;
    const int tq = lane & 3;
    __half* ob = o + ((size_t)b * 144 + wrow + g) * 512 + h * 64 + tq * 2;
#pragma unroll
    for (int dt = 0; dt < 8; dt++) {
        __half2 h0 = __floats2half2_rn(oacc[dt][0] * inv0, oacc[dt][1] * inv0);
        __half2 h1 = __floats2half2_rn(oacc[dt][2] * inv1, oacc[dt][3] * inv1);
        *(__half2*)(ob + dt * 8)             = h0;
        *(__half2*)(ob + 8 * 512 + dt * 8)   = h1;
    }
}

// ---------------- launch -------------------------------------------------------
extern "C" void kernel_launch(void* const* d_in, const int* in_sizes, int n_in,
                              void* d_out, int out_size)
{
    const float* x      = (const float*)d_in[0];
    const float* topo   = (const float*)d_in[1];
    const float* kv_w   = (const float*)d_in[2];
    const float* q_w    = (const float*)d_in[3];
    const float* proj_w = (const float*)d_in[4];
    const float* proj_b = (const float*)d_in[5];
    const int*   is_end = (const int*)d_in[6];

    void *pkvh, *pqh, *pxteh, *pxh, *pah, *pwkv, *pwq, *pwp;
    cudaGetSymbolAddress(&pkvh,  g_kvh);
    cudaGetSymbolAddress(&pqh,   g_qh);
    cudaGetSymbolAddress(&pxteh, g_xteh);
    cudaGetSymbolAddress(&pxh,   g_xh);
    cudaGetSymbolAddress(&pah,   g_ah);
    cudaGetSymbolAddress(&pwkv,  g_wkvh);
    cudaGetSymbolAddress(&pwq,   g_wqh);
    cudaGetSymbolAddress(&pwp,   g_wph);

    cudaFuncSetAttribute(attn_kernel, cudaFuncAttributeMaxDynamicSharedMemorySize,
                         ATTN_SMEM_BYTES);
    cudaFuncSetAttribute(gemm_mma_kernel<true>,
                         cudaFuncAttributeMaxDynamicSharedMemorySize, GEMM_SMEM);
    cudaFuncSetAttribute(gemm_mma_kernel<false>,
                         cudaFuncAttributeMaxDynamicSharedMemorySize, GEMM_SMEM);

    const long act4 = (long)M_ * 512 / 4;
    const int  TB   = 256;

    prep_x_kernel<<<(unsigned)((act4 + TB - 1) / TB), TB>>>(
        (const float4*)x, (const float4*)topo, is_end,
        (__half*)pxteh, (__half*)pxh, act4);
    prep_w_kernel<<<(unsigned)((WTOT4 + TB - 1) / TB), TB>>>(
        (const float4*)kv_w, (const float4*)q_w, (const float4*)proj_w,
        (__half*)pwkv, (__half*)pwq, (__half*)pwp);

    gemm_mma_kernel<true><<<dim3(8, 288), 256, GEMM_SMEM>>>(
        (const __half*)pxteh, (const __half*)pwkv, nullptr, pkvh, 1024);
    gemm_mma_kernel<true><<<dim3(4, 288), 256, GEMM_SMEM>>>(
        (const __half*)pxh, (const __half*)pwq, nullptr, pqh, 512);
    attn_kernel<<<B_ * 8, 288, ATTN_SMEM_BYTES>>>(
        (const __half*)pqh, (const __half*)pkvh, (__half*)pah);
    gemm_mma_kernel<false><<<dim3(4, 288), 256, GEMM_SMEM>>>(
        (const __half*)pah, (const __half*)pwp, proj_b, d_out, 512);
}